// round 13
// baseline (speedup 1.0000x reference)
#include <cuda_runtime.h>
#include <cuda_fp16.h>
#include <cfloat>
#include <cstdint>

// Problem constants
#define Bb 8
#define Hh 8
#define Nn 4096
#define Dd 64
#define Mm 64
#define Pp (Bb*Hh)        // 64 (b,h) pairs
#define KSPLIT 8

#define HSTR 36           // half2-word stride: frag reads land on banks 4g+tg (conflict-free)

// ---------------- scratch (device globals) ----------------
__device__ float g_sK [Pp*Nn];
__device__ float g_sQ [Pp*Nn];
__device__ int   g_idxK[Pp*Mm];
__device__ int   g_idxQ[Pp*Mm];
__device__ float g_nc [Pp*Mm*Dd];         // column landmarks (rows of K)
__device__ float g_nr [Pp*Mm*Dd];         // row landmarks (rows of Qs, pre-scaled 1/8)
__device__ float g_u  [Pp*Mm*Mm];
__device__ float g_rvp[(size_t)Pp*KSPLIT*Mm*Dd]; // unnormalized RV partials
__device__ float g_rss[Pp*KSPLIT*Mm];            // rowsum-of-exp partials
__device__ float g_w  [Pp*Mm*Dd];
__device__ unsigned int g_smax;

// ---------------- fp16 split helpers ----------------
__device__ __forceinline__ void h2split(float x, float y, uint32_t& h, uint32_t& l) {
    __half hx = __float2half_rn(x), hy = __float2half_rn(y);
    float rx = x - __half2float(hx), ry = y - __half2float(hy);
    __half lx = __float2half_rn(rx), ly = __float2half_rn(ry);
    h = (uint32_t)__half_as_ushort(hx) | ((uint32_t)__half_as_ushort(hy) << 16);
    l = (uint32_t)__half_as_ushort(lx) | ((uint32_t)__half_as_ushort(ly) << 16);
}

__device__ __forceinline__ void mma_f16(float* d, uint32_t a0, uint32_t a1, uint32_t a2, uint32_t a3,
                                        uint32_t b0, uint32_t b1) {
    asm volatile(
        "mma.sync.aligned.m16n8k16.row.col.f32.f16.f16.f32 "
        "{%0,%1,%2,%3},{%4,%5,%6,%7},{%8,%9},{%0,%1,%2,%3};"
        : "+f"(d[0]), "+f"(d[1]), "+f"(d[2]), "+f"(d[3])
        : "r"(a0), "r"(a1), "r"(a2), "r"(a3), "r"(b0), "r"(b1));
}
// fp16x3: D += Ah*Bh + Ah*Bl + Al*Bh
__device__ __forceinline__ void mma3(float* d, const uint32_t* ah, const uint32_t* al,
                                     uint32_t bh0, uint32_t bh1, uint32_t bl0, uint32_t bl1) {
    mma_f16(d, ah[0], ah[1], ah[2], ah[3], bh0, bh1);
    mma_f16(d, ah[0], ah[1], ah[2], ah[3], bl0, bl1);
    mma_f16(d, al[0], al[1], al[2], al[3], bh0, bh1);
}
__device__ __forceinline__ void ldsm2t(uint32_t& r0, uint32_t& r1, uint32_t saddr) {
    asm volatile("ldmatrix.sync.aligned.m8n8.x2.trans.shared.b16 {%0,%1}, [%2];"
                 : "=r"(r0), "=r"(r1) : "r"(saddr));
}
__device__ __forceinline__ void afrag(const uint32_t* H, const uint32_t* L, int r0, int kp0,
                                      uint32_t* ah, uint32_t* al) {
    ah[0] = H[r0 * HSTR + kp0];       al[0] = L[r0 * HSTR + kp0];
    ah[1] = H[(r0 + 8) * HSTR + kp0]; al[1] = L[(r0 + 8) * HSTR + kp0];
    ah[2] = H[r0 * HSTR + kp0 + 4];       al[2] = L[r0 * HSTR + kp0 + 4];
    ah[3] = H[(r0 + 8) * HSTR + kp0 + 4]; al[3] = L[(r0 + 8) * HSTR + kp0 + 4];
}

// ---------------- 1) scores ----------------
__global__ void scores_k(const float* __restrict__ Q, const float* __restrict__ K) {
    if (blockIdx.x == 0 && threadIdx.x == 0 && threadIdx.y == 0) g_smax = 0u;
    int row = blockIdx.x * 8 + threadIdx.y;
    if (row >= Pp * Nn) return;
    int lane = threadIdx.x;
    const float* q = Q + (size_t)row * Dd;
    const float* k = K + (size_t)row * Dd;
    float sq = q[lane] + q[lane + 32];
    float sk = k[lane] + k[lane + 32];
    #pragma unroll
    for (int o = 16; o; o >>= 1) {
        sq += __shfl_xor_sync(0xffffffffu, sq, o);
        sk += __shfl_xor_sync(0xffffffffu, sk, o);
    }
    if (lane == 0) { g_sQ[row] = sq; g_sK[row] = sk; }
}

// ---------------- 2) top-64 via 4-pass radix select ----------------
__global__ void __launch_bounds__(256) topk_k() {
    __shared__ unsigned key[Nn];
    __shared__ unsigned hist[256];
    __shared__ unsigned sh_pref;
    __shared__ int      sh_krem;
    __shared__ unsigned sh_cnt, sh_tie;
    __shared__ int      tiebuf[64];
    int p   = blockIdx.x & (Pp - 1);
    bool isK = blockIdx.x < Pp;
    const float* src = (isK ? g_sK : g_sQ) + (size_t)p * Nn;
    int* dst = (isK ? g_idxK : g_idxQ) + p * Mm;
    int t = threadIdx.x;
    for (int i = t; i < Nn; i += 256) {
        unsigned u = __float_as_uint(src[i]);
        key[i] = u ^ ((unsigned)((int)u >> 31) | 0x80000000u);
    }
    if (t == 0) { sh_pref = 0u; sh_krem = Mm; sh_cnt = 0u; sh_tie = 0u; }
    __syncthreads();
    #pragma unroll
    for (int b = 3; b >= 0; b--) {
        hist[t] = 0u;
        __syncthreads();
        unsigned maskHi = (b == 3) ? 0u : (0xFFFFFFFFu << ((b + 1) * 8));
        unsigned pref = sh_pref;
        for (int i = t; i < Nn; i += 256) {
            unsigned k = key[i];
            if ((k & maskHi) == pref)
                atomicAdd(&hist[(k >> (b * 8)) & 0xFFu], 1u);
        }
        __syncthreads();
        if (t == 0) {
            int krem = sh_krem, acc = 0, bsel = 0;
            for (int bin = 255; bin >= 0; bin--) {
                int c = (int)hist[bin];
                if (acc + c >= krem) { bsel = bin; break; }
                acc += c;
            }
            sh_krem = krem - acc;
            sh_pref = sh_pref | ((unsigned)bsel << (b * 8));
        }
        __syncthreads();
    }
    unsigned T = sh_pref;
    for (int i = t; i < Nn; i += 256) {
        unsigned k = key[i];
        if (k > T) {
            unsigned pos = atomicAdd(&sh_cnt, 1u);
            dst[pos] = i;
        } else if (k == T) {
            unsigned tp = atomicAdd(&sh_tie, 1u);
            if (tp < 64u) tiebuf[tp] = i;
        }
    }
    __syncthreads();
    if (t == 0) {
        int n = (int)min(sh_tie, 64u);
        for (int i = 1; i < n; i++) {
            int v = tiebuf[i], j = i - 1;
            while (j >= 0 && tiebuf[j] > v) { tiebuf[j + 1] = tiebuf[j]; j--; }
            tiebuf[j + 1] = v;
        }
        int base = (int)sh_cnt, krem = sh_krem;
        for (int j = 0; j < krem; j++) dst[base + j] = tiebuf[j];
    }
}

// ---------------- float4 64x64x64 smem GEMM, 256 threads (stride 68): C = A @ B ----------------
__device__ __forceinline__ void mm64(float* C, const float* A, const float* B, int t) {
    int tx = t & 15, ty = t >> 4, r0 = ty * 4, c0 = tx * 4;
    float acc[4][4] = {};
    #pragma unroll
    for (int k0 = 0; k0 < 64; k0 += 4) {
        float4 a[4], b[4];
        #pragma unroll
        for (int i = 0; i < 4; i++) a[i] = *(const float4*)&A[(r0 + i) * 68 + k0];
        #pragma unroll
        for (int kk = 0; kk < 4; kk++) b[kk] = *(const float4*)&B[(k0 + kk) * 68 + c0];
        #pragma unroll
        for (int i = 0; i < 4; i++) {
            float av[4] = {a[i].x, a[i].y, a[i].z, a[i].w};
            #pragma unroll
            for (int kk = 0; kk < 4; kk++) {
                float bv[4] = {b[kk].x, b[kk].y, b[kk].z, b[kk].w};
                #pragma unroll
                for (int j = 0; j < 4; j++) acc[i][j] += av[kk] * bv[j];
            }
        }
    }
    #pragma unroll
    for (int i = 0; i < 4; i++)
        *(float4*)&C[(r0 + i) * 68 + c0] = make_float4(acc[i][0], acc[i][1], acc[i][2], acc[i][3]);
    __syncthreads();
}

// ---------------- 3) gather landmarks + u = row_softmax(nr @ nc^T) + colsum/smax ----------------
__global__ void __launch_bounds__(256) gather_u_k(const float* __restrict__ Q,
                                                  const float* __restrict__ K) {
    extern __shared__ float sm[];
    float* snr  = sm;             // [64 m][68]
    float* sncT = sm + 4352;      // [64 k][68]
    float* su   = sm + 8704;      // [64][68]
    int p = blockIdx.x, t = threadIdx.x;
    const int* idxK = g_idxK + p * Mm;
    const int* idxQ = g_idxQ + p * Mm;
    for (int e = t; e < 4096; e += 256) {
        int m = e >> 6, d = e & 63;
        float vnc = K[((size_t)p * Nn + idxK[m]) * Dd + d];
        float vnr = Q[((size_t)p * Nn + idxQ[m]) * Dd + d] * 0.125f;
        g_nc[p * 4096 + e] = vnc;
        g_nr[p * 4096 + e] = vnr;
        snr[m * 68 + d] = vnr;
        sncT[d * 68 + m] = vnc;
    }
    __syncthreads();
    mm64(su, snr, sncT, t);
    if (t < 64) {
        float mx = -FLT_MAX;
        for (int c = 0; c < 64; c++) mx = fmaxf(mx, su[t * 68 + c]);
        float s = 0.f;
        for (int c = 0; c < 64; c++) s += __expf(su[t * 68 + c] - mx);
        float inv = 1.f / s;
        for (int c = 0; c < 64; c++) {
            float v = __expf(su[t * 68 + c] - mx) * inv;
            su[t * 68 + c] = v;
            g_u[p * 4096 + t * 64 + c] = v;
        }
    }
    __syncthreads();
    if (t < 64) {
        float cs = 0.f;
        for (int i = 0; i < 64; i++) cs += su[i * 68 + t];
        atomicMax((int*)&g_smax, __float_as_int(cs));
    }
}
#define GU_SMEM_BYTES (3 * 4352 * 4)

// ---------------- 4) flash RV (fp16x3, R9 structure): Σ exp(nr@K^T)·V over an N-chunk ----------------
__global__ void __launch_bounds__(256, 4) flash_rv_k(const float* __restrict__ K,
                                                     const float* __restrict__ V) {
    extern __shared__ uint32_t smu[];
    uint32_t* AsH = smu;            // nr split [64 m][HSTR]
    uint32_t* AsL = smu + 2304;
    uint32_t* PsH = smu + 4608;     // P split  [64 m][HSTR]
    uint32_t* PsL = smu + 6912;
    uint32_t* BsH = smu + 9216;     // K then V [64 rows][HSTR]
    uint32_t* BsL = smu + 11520;
    float*    red = (float*)(smu + 9216);   // aliases Bs (dead after the nt loop)
    int p  = blockIdx.x >> 3;
    int ch = blockIdx.x & 7;
    int t = threadIdx.x;
    for (int e = t; e < 2048; e += 256) {
        int m = e >> 5, kp = e & 31;
        float2 v = *(const float2*)&g_nr[p * 4096 + m * 64 + 2 * kp];
        h2split(v.x, v.y, AsH[m * HSTR + kp], AsL[m * HSTR + kp]);
    }
    const float* Kp = K + (size_t)p * Nn * Dd;
    const float* Vp = V + (size_t)p * Nn * Dd;
    int w = t >> 5, lane = t & 31, g = lane >> 2, tg = lane & 3;
    int mt = w & 3, nh = w >> 2;
    int r0 = mt * 16 + g;
    int lrow = lane & 15;
    uint32_t vbH = (uint32_t)__cvta_generic_to_shared(BsH);
    uint32_t vbL = (uint32_t)__cvta_generic_to_shared(BsL);
    float dRV[4][4] = {};
    float rs0 = 0.f, rs1 = 0.f;
    for (int nt = 0; nt < 8; nt++) {
        int nb = ch * 512 + nt * 64;
        __syncthreads();                        // prior RV-MMA done before Bs overwrite
        for (int e = t; e < 2048; e += 256) {   // Bs = K rows: [n][k-pairs]
            int n = e >> 5, kp = e & 31;
            float2 v = *(const float2*)&Kp[(size_t)(nb + n) * Dd + 2 * kp];
            h2split(v.x, v.y, BsH[n * HSTR + kp], BsL[n * HSTR + kp]);
        }
        __syncthreads();
        // S = nr @ K^T
        float dS[4][4] = {};
        #pragma unroll
        for (int ks = 0; ks < 4; ks++) {
            int kp0 = 8 * ks + tg;
            uint32_t ah[4], al[4];
            afrag(AsH, AsL, r0, kp0, ah, al);
            #pragma unroll
            for (int j = 0; j < 4; j++) {
                int c = nh * 32 + j * 8 + g;
                mma3(dS[j], ah, al,
                     BsH[c * HSTR + kp0], BsH[c * HSTR + kp0 + 4],
                     BsL[c * HSTR + kp0], BsL[c * HSTR + kp0 + 4]);
            }
        }
        // P = exp(S) (unnormalized; |S| small), rowsums, split-store
        #pragma unroll
        for (int j = 0; j < 4; j++) {
            int np = nh * 16 + j * 4 + tg;
            float e00 = __expf(dS[j][0]), e01 = __expf(dS[j][1]);
            float e10 = __expf(dS[j][2]), e11 = __expf(dS[j][3]);
            rs0 += e00 + e01; rs1 += e10 + e11;
            h2split(e00, e01, PsH[r0 * HSTR + np], PsL[r0 * HSTR + np]);
            h2split(e10, e11, PsH[(r0 + 8) * HSTR + np], PsL[(r0 + 8) * HSTR + np]);
        }
        __syncthreads();                        // P complete; Bs free
        for (int e = t; e < 2048; e += 256) {   // Bs = V rows: [n][d-pairs]
            int n = e >> 5, dp = e & 31;
            float2 v = *(const float2*)&Vp[(size_t)(nb + n) * Dd + 2 * dp];
            h2split(v.x, v.y, BsH[n * HSTR + dp], BsL[n * HSTR + dp]);
        }
        __syncthreads();
        // RV += P @ V  (B frag via ldmatrix.trans on V's [k=n][d] rows)
        #pragma unroll
        for (int ks = 0; ks < 4; ks++) {
            int kp0 = 8 * ks + tg;
            uint32_t ah[4], al[4];
            afrag(PsH, PsL, r0, kp0, ah, al);
            int krow = 16 * ks + lrow;
            #pragma unroll
            for (int j = 0; j < 4; j++) {
                uint32_t off = (uint32_t)((krow * HSTR + nh * 16 + j * 4) * 4);
                uint32_t bh0, bh1, bl0, bl1;
                ldsm2t(bh0, bh1, vbH + off);
                ldsm2t(bl0, bl1, vbL + off);
                mma3(dRV[j], ah, al, bh0, bh1, bl0, bl1);
            }
        }
    }
    #pragma unroll
    for (int o = 1; o <= 2; o <<= 1) {
        rs0 += __shfl_xor_sync(0xffffffffu, rs0, o);
        rs1 += __shfl_xor_sync(0xffffffffu, rs1, o);
    }
    __syncthreads();                            // all RV-MMA Bs reads done; red may alias Bs now
    if (tg == 0) { red[nh * 64 + r0] = rs0; red[nh * 64 + r0 + 8] = rs1; }
    __syncthreads();
    if (t < 64) g_rss[(p * KSPLIT + ch) * 64 + t] = red[t] + red[64 + t];
    float* out = g_rvp + ((size_t)blockIdx.x << 12);
    #pragma unroll
    for (int j = 0; j < 4; j++) {
        int cb = nh * 32 + j * 8 + 2 * tg;
        *(float2*)&out[r0 * 64 + cb]       = make_float2(dRV[j][0], dRV[j][1]);
        *(float2*)&out[(r0 + 8) * 64 + cb] = make_float2(dRV[j][2], dRV[j][3]);
    }
}
#define FLASH_SMEM_BYTES (13824 * 4)

// ---------------- 5) Newton-Schulz (+ fused RV merge) + W = Vinv @ RV ----------------
__global__ void __launch_bounds__(256) newton_k() {
    extern __shared__ float sm[];
    float* sKm  = sm;
    float* sV   = sm + 4352;
    float* sA   = sm + 8704;
    float* sT1  = sm + 13056;
    float* sT2  = sm + 17408;
    float* sden = sm + 21760;
    int p = blockIdx.x;
    int t = threadIdx.x;
    if (t < 64) {
        float den = 0.f;
        #pragma unroll
        for (int ch = 0; ch < KSPLIT; ch++) den += g_rss[(p * KSPLIT + ch) * 64 + t];
        sden[t] = 1.f / den;
    }
    for (int e = t; e < 4096; e += 256) {
        int r = e >> 6, c = e & 63;
        sKm[r * 68 + c] = g_u[p * 4096 + e];
    }
    __syncthreads();
    float invs = 1.f / __int_as_float((int)g_smax);
    for (int e = t; e < 4096; e += 256) {
        int r = e >> 6, c = e & 63;
        sV[r * 68 + c] = sKm[c * 68 + r] * invs;
    }
    __syncthreads();
    for (int it = 0; it < 6; it++) {
        mm64(sA, sKm, sV, t);
        for (int e = t; e < 4096; e += 256) {
            int r = e >> 6, c = e & 63;
            sT1[r * 68 + c] = (r == c ? 7.f : 0.f) - sA[r * 68 + c];
        }
        __syncthreads();
        mm64(sT2, sA, sT1, t);
        for (int e = t; e < 4096; e += 256) {
            int r = e >> 6, c = e & 63;
            sT1[r * 68 + c] = (r == c ? 15.f : 0.f) - sT2[r * 68 + c];
        }
        __syncthreads();
        mm64(sT2, sA, sT1, t);
        for (int e = t; e < 4096; e += 256) {
            int r = e >> 6, c = e & 63;
            sT1[r * 68 + c] = (r == c ? 13.f : 0.f) - sT2[r * 68 + c];
        }
        __syncthreads();
        mm64(sT2, sV, sT1, t);
        for (int e = t; e < 4096; e += 256) {
            int r = e >> 6, c = e & 63;
            sV[r * 68 + c] = 0.25f * sT2[r * 68 + c];
        }
        __syncthreads();
    }
    for (int e = t; e < 4096; e += 256) {
        int r = e >> 6, c = e & 63;
        float s = 0.f;
        #pragma unroll
        for (int ch = 0; ch < KSPLIT; ch++) s += g_rvp[((size_t)(p * KSPLIT + ch) << 12) + e];
        sT1[r * 68 + c] = s * sden[r];
    }
    __syncthreads();
    mm64(sT2, sV, sT1, t);
    for (int e = t; e < 4096; e += 256) {
        int r = e >> 6, c = e & 63;
        g_w[p * 4096 + e] = sT2[r * 68 + c];
    }
}
#define NEWTON_SMEM_BYTES ((5 * 4352 + 64) * 4)

// ---------------- 6) fused X (fp16x3): c -> softmax -> @W -> out ----------------
__global__ void __launch_bounds__(256, 3) x_fused_k(const float* __restrict__ Q,
                                                    float* __restrict__ out) {
    extern __shared__ uint32_t smu[];
    uint32_t* AsH = smu;            // Q tile, then k1 tile [128][HSTR]
    uint32_t* AsL = smu + 4608;
    uint32_t* BsH = smu + 9216;     // nc, then W [64][HSTR]
    uint32_t* BsL = smu + 11520;
    int p  = blockIdx.x >> 5;
    int n0 = (blockIdx.x & 31) * 128;
    int t = threadIdx.x;
    const float* Ag = Q + ((size_t)p * Nn + n0) * Dd;
    for (int e = t; e < 4096; e += 256) {
        int m = e >> 5, kp = e & 31;
        float2 v = *(const float2*)&Ag[m * 64 + 2 * kp];
        h2split(v.x * 0.125f, v.y * 0.125f, AsH[m * HSTR + kp], AsL[m * HSTR + kp]);
    }
    const float* Bg = g_nc + (size_t)p * Mm * Dd;
    for (int e = t; e < 2048; e += 256) {
        int c = e >> 5, kp = e & 31;
        float2 v = *(const float2*)&Bg[c * 64 + 2 * kp];
        h2split(v.x, v.y, BsH[c * HSTR + kp], BsL[c * HSTR + kp]);
    }
    __syncthreads();
    int w = t >> 5, lane = t & 31, g = lane >> 2, tg = lane & 3;
    int r0 = w * 16 + g;
    int lrow = lane & 15;
    // GEMM 1: c = Qs @ nc^T
    float d[8][4] = {};
    #pragma unroll
    for (int ks = 0; ks < 4; ks++) {
        int kp0 = 8 * ks + tg;
        uint32_t ah[4], al[4];
        afrag(AsH, AsL, r0, kp0, ah, al);
        #pragma unroll
        for (int j = 0; j < 8; j++) {
            int c = j * 8 + g;
            mma3(d[j], ah, al,
                 BsH[c * HSTR + kp0], BsH[c * HSTR + kp0 + 4],
                 BsL[c * HSTR + kp0], BsL[c * HSTR + kp0 + 4]);
        }
    }
    // exact row softmax over the 4-lane group
    float mx0 = -FLT_MAX, mx1 = -FLT_MAX;
    #pragma unroll
    for (int j = 0; j < 8; j++) {
        mx0 = fmaxf(mx0, fmaxf(d[j][0], d[j][1]));
        mx1 = fmaxf(mx1, fmaxf(d[j][2], d[j][3]));
    }
    #pragma unroll
    for (int o = 1; o <= 2; o <<= 1) {
        mx0 = fmaxf(mx0, __shfl_xor_sync(0xffffffffu, mx0, o));
        mx1 = fmaxf(mx1, __shfl_xor_sync(0xffffffffu, mx1, o));
    }
    float s0 = 0.f, s1 = 0.f;
    #pragma unroll
    for (int j = 0; j < 8; j++) {
        d[j][0] = __expf(d[j][0] - mx0); d[j][1] = __expf(d[j][1] - mx0);
        d[j][2] = __expf(d[j][2] - mx1); d[j][3] = __expf(d[j][3] - mx1);
        s0 += d[j][0] + d[j][1];
        s1 += d[j][2] + d[j][3];
    }
    #pragma unroll
    for (int o = 1; o <= 2; o <<= 1) {
        s0 += __shfl_xor_sync(0xffffffffu, s0, o);
        s1 += __shfl_xor_sync(0xffffffffu, s1, o);
    }
    float i0 = 1.f / s0, i1 = 1.f / s1;
    // store k1 split into As (warp-private rows; n-adjacent pairs)
    #pragma unroll
    for (int j = 0; j < 8; j++) {
        int np = j * 4 + tg;
        h2split(d[j][0] * i0, d[j][1] * i0, AsH[r0 * HSTR + np], AsL[r0 * HSTR + np]);
        h2split(d[j][2] * i1, d[j][3] * i1, AsH[(r0 + 8) * HSTR + np], AsL[(r0 + 8) * HSTR + np]);
    }
    // reuse d as the GEMM-2 accumulator (register save)
    #pragma unroll
    for (int j = 0; j < 8; j++)
        #pragma unroll
        for (int q = 0; q < 4; q++) d[j][q] = 0.f;
    __syncthreads();                 // all warps done with Bs(nc); k1 stores visible
    const float* Wg = g_w + (size_t)p * Mm * Dd;
    for (int e = t; e < 2048; e += 256) {
        int k = e >> 5, dp = e & 31;
        float2 v = *(const float2*)&Wg[k * 64 + 2 * dp];
        h2split(v.x, v.y, BsH[k * HSTR + dp], BsL[k * HSTR + dp]);
    }
    __syncthreads();
    uint32_t wbH = (uint32_t)__cvta_generic_to_shared(BsH);
    uint32_t wbL = (uint32_t)__cvta_generic_to_shared(BsL);
    // GEMM 2: X = k1 @ W
    #pragma unroll
    for (int ks = 0; ks < 4; ks++) {
        int kp0 = 8 * ks + tg;
        uint32_t ah[4], al[4];
        afrag(AsH, AsL, r0, kp0, ah, al);
        int krow = 16 * ks + lrow;
        #pragma unroll
        for (int j = 0; j < 8; j++) {
            uint32_t off = (uint32_t)((krow * HSTR + j * 4) * 4);
            uint32_t bh0, bh1, bl0, bl1;
            ldsm2t(bh0, bh1, wbH + off);
            ldsm2t(bl0, bl1, wbL + off);
            mma3(d[j], ah, al, bh0, bh1, bl0, bl1);
        }
    }
    size_t row0 = (size_t)p * Nn + n0 + r0;
    #pragma unroll
    for (int j = 0; j < 8; j++) {
        int c0 = j * 8 + 2 * tg;
        *(float2*)&out[row0 * Dd + c0]       = make_float2(d[j][0], d[j][1]);
        *(float2*)&out[(row0 + 8) * Dd + c0] = make_float2(d[j][2], d[j][3]);
    }
}
#define XF_SMEM_BYTES (13824 * 4)

// ---------------- launch ----------------
extern "C" void kernel_launch(void* const* d_in, const int* in_sizes, int n_in,
                              void* d_out, int out_size) {
    const float* Q = (const float*)d_in[0];
    const float* K = (const float*)d_in[1];
    const float* V = (const float*)d_in[2];
    float* out = (float*)d_out;

    cudaFuncSetAttribute(gather_u_k, cudaFuncAttributeMaxDynamicSharedMemorySize, GU_SMEM_BYTES);
    cudaFuncSetAttribute(flash_rv_k, cudaFuncAttributeMaxDynamicSharedMemorySize, FLASH_SMEM_BYTES);
    cudaFuncSetAttribute(newton_k,   cudaFuncAttributeMaxDynamicSharedMemorySize, NEWTON_SMEM_BYTES);
    cudaFuncSetAttribute(x_fused_k,  cudaFuncAttributeMaxDynamicSharedMemorySize, XF_SMEM_BYTES);

    scores_k  <<<Pp * Nn / 8, dim3(32, 8)>>>(Q, K);
    topk_k    <<<2 * Pp, 256>>>();
    gather_u_k<<<Pp, 256, GU_SMEM_BYTES>>>(Q, K);
    flash_rv_k<<<Pp * KSPLIT, 256, FLASH_SMEM_BYTES>>>(K, V);
    newton_k  <<<Pp, 256, NEWTON_SMEM_BYTES>>>();
    x_fused_k <<<Pp * 32, 256, XF_SMEM_BYTES>>>(Q, out);
}

// round 14
// speedup vs baseline: 1.0362x; 1.0362x over previous
#include <cuda_runtime.h>
#include <cuda_fp16.h>
#include <cfloat>
#include <cstdint>

// Problem constants
#define Bb 8
#define Hh 8
#define Nn 4096
#define Dd 64
#define Mm 64
#define Pp (Bb*Hh)        // 64 (b,h) pairs
#define KSPLIT 8

#define HSTR 36           // half2-word stride: frag reads land on banks 4g+tg (conflict-free)

// ---------------- scratch (device globals) ----------------
__device__ float g_sK [Pp*Nn];
__device__ float g_sQ [Pp*Nn];
__device__ int   g_idxK[Pp*Mm];
__device__ int   g_idxQ[Pp*Mm];
__device__ float g_nc [Pp*Mm*Dd];         // column landmarks (rows of K)
__device__ float g_nr [Pp*Mm*Dd];         // row landmarks (rows of Qs, pre-scaled 1/8)
__device__ float g_u  [Pp*Mm*Mm];
__device__ float g_rvp[(size_t)Pp*KSPLIT*Mm*Dd]; // unnormalized RV partials
__device__ float g_rss[Pp*KSPLIT*Mm];            // rowsum-of-exp partials
__device__ float g_w  [Pp*Mm*Dd];
__device__ unsigned int g_smax;

// ---------------- fp16 split helpers ----------------
__device__ __forceinline__ void h2split(float x, float y, uint32_t& h, uint32_t& l) {
    __half hx = __float2half_rn(x), hy = __float2half_rn(y);
    float rx = x - __half2float(hx), ry = y - __half2float(hy);
    __half lx = __float2half_rn(rx), ly = __float2half_rn(ry);
    h = (uint32_t)__half_as_ushort(hx) | ((uint32_t)__half_as_ushort(hy) << 16);
    l = (uint32_t)__half_as_ushort(lx) | ((uint32_t)__half_as_ushort(ly) << 16);
}

__device__ __forceinline__ void mma_f16(float* d, uint32_t a0, uint32_t a1, uint32_t a2, uint32_t a3,
                                        uint32_t b0, uint32_t b1) {
    asm volatile(
        "mma.sync.aligned.m16n8k16.row.col.f32.f16.f16.f32 "
        "{%0,%1,%2,%3},{%4,%5,%6,%7},{%8,%9},{%0,%1,%2,%3};"
        : "+f"(d[0]), "+f"(d[1]), "+f"(d[2]), "+f"(d[3])
        : "r"(a0), "r"(a1), "r"(a2), "r"(a3), "r"(b0), "r"(b1));
}
// fp16x3: D += Ah*Bh + Ah*Bl + Al*Bh
__device__ __forceinline__ void mma3(float* d, const uint32_t* ah, const uint32_t* al,
                                     uint32_t bh0, uint32_t bh1, uint32_t bl0, uint32_t bl1) {
    mma_f16(d, ah[0], ah[1], ah[2], ah[3], bh0, bh1);
    mma_f16(d, ah[0], ah[1], ah[2], ah[3], bl0, bl1);
    mma_f16(d, al[0], al[1], al[2], al[3], bh0, bh1);
}
__device__ __forceinline__ void ldsm2t(uint32_t& r0, uint32_t& r1, uint32_t saddr) {
    asm volatile("ldmatrix.sync.aligned.m8n8.x2.trans.shared.b16 {%0,%1}, [%2];"
                 : "=r"(r0), "=r"(r1) : "r"(saddr));
}
__device__ __forceinline__ void afrag(const uint32_t* H, const uint32_t* L, int r0, int kp0,
                                      uint32_t* ah, uint32_t* al) {
    ah[0] = H[r0 * HSTR + kp0];       al[0] = L[r0 * HSTR + kp0];
    ah[1] = H[(r0 + 8) * HSTR + kp0]; al[1] = L[(r0 + 8) * HSTR + kp0];
    ah[2] = H[r0 * HSTR + kp0 + 4];       al[2] = L[r0 * HSTR + kp0 + 4];
    ah[3] = H[(r0 + 8) * HSTR + kp0 + 4]; al[3] = L[(r0 + 8) * HSTR + kp0 + 4];
}

// ---------------- 1) scores ----------------
__global__ void scores_k(const float* __restrict__ Q, const float* __restrict__ K) {
    if (blockIdx.x == 0 && threadIdx.x == 0 && threadIdx.y == 0) g_smax = 0u;
    int row = blockIdx.x * 8 + threadIdx.y;
    if (row >= Pp * Nn) return;
    int lane = threadIdx.x;
    const float* q = Q + (size_t)row * Dd;
    const float* k = K + (size_t)row * Dd;
    float sq = q[lane] + q[lane + 32];
    float sk = k[lane] + k[lane + 32];
    #pragma unroll
    for (int o = 16; o; o >>= 1) {
        sq += __shfl_xor_sync(0xffffffffu, sq, o);
        sk += __shfl_xor_sync(0xffffffffu, sk, o);
    }
    if (lane == 0) { g_sQ[row] = sq; g_sK[row] = sk; }
}

// ---------------- 2) top-64 via 4-pass radix select ----------------
__global__ void __launch_bounds__(256) topk_k() {
    __shared__ unsigned key[Nn];
    __shared__ unsigned hist[256];
    __shared__ unsigned sh_pref;
    __shared__ int      sh_krem;
    __shared__ unsigned sh_cnt, sh_tie;
    __shared__ int      tiebuf[64];
    int p   = blockIdx.x & (Pp - 1);
    bool isK = blockIdx.x < Pp;
    const float* src = (isK ? g_sK : g_sQ) + (size_t)p * Nn;
    int* dst = (isK ? g_idxK : g_idxQ) + p * Mm;
    int t = threadIdx.x;
    for (int i = t; i < Nn; i += 256) {
        unsigned u = __float_as_uint(src[i]);
        key[i] = u ^ ((unsigned)((int)u >> 31) | 0x80000000u);
    }
    if (t == 0) { sh_pref = 0u; sh_krem = Mm; sh_cnt = 0u; sh_tie = 0u; }
    __syncthreads();
    #pragma unroll
    for (int b = 3; b >= 0; b--) {
        hist[t] = 0u;
        __syncthreads();
        unsigned maskHi = (b == 3) ? 0u : (0xFFFFFFFFu << ((b + 1) * 8));
        unsigned pref = sh_pref;
        for (int i = t; i < Nn; i += 256) {
            unsigned k = key[i];
            if ((k & maskHi) == pref)
                atomicAdd(&hist[(k >> (b * 8)) & 0xFFu], 1u);
        }
        __syncthreads();
        if (t == 0) {
            int krem = sh_krem, acc = 0, bsel = 0;
            for (int bin = 255; bin >= 0; bin--) {
                int c = (int)hist[bin];
                if (acc + c >= krem) { bsel = bin; break; }
                acc += c;
            }
            sh_krem = krem - acc;
            sh_pref = sh_pref | ((unsigned)bsel << (b * 8));
        }
        __syncthreads();
    }
    unsigned T = sh_pref;
    for (int i = t; i < Nn; i += 256) {
        unsigned k = key[i];
        if (k > T) {
            unsigned pos = atomicAdd(&sh_cnt, 1u);
            dst[pos] = i;
        } else if (k == T) {
            unsigned tp = atomicAdd(&sh_tie, 1u);
            if (tp < 64u) tiebuf[tp] = i;
        }
    }
    __syncthreads();
    if (t == 0) {
        int n = (int)min(sh_tie, 64u);
        for (int i = 1; i < n; i++) {
            int v = tiebuf[i], j = i - 1;
            while (j >= 0 && tiebuf[j] > v) { tiebuf[j + 1] = tiebuf[j]; j--; }
            tiebuf[j + 1] = v;
        }
        int base = (int)sh_cnt, krem = sh_krem;
        for (int j = 0; j < krem; j++) dst[base + j] = tiebuf[j];
    }
}

// ---------------- float4 64x64x64 smem GEMM, 256 threads (stride 68): C = A @ B ----------------
__device__ __forceinline__ void mm64(float* C, const float* A, const float* B, int t) {
    int tx = t & 15, ty = t >> 4, r0 = ty * 4, c0 = tx * 4;
    float acc[4][4] = {};
    #pragma unroll
    for (int k0 = 0; k0 < 64; k0 += 4) {
        float4 a[4], b[4];
        #pragma unroll
        for (int i = 0; i < 4; i++) a[i] = *(const float4*)&A[(r0 + i) * 68 + k0];
        #pragma unroll
        for (int kk = 0; kk < 4; kk++) b[kk] = *(const float4*)&B[(k0 + kk) * 68 + c0];
        #pragma unroll
        for (int i = 0; i < 4; i++) {
            float av[4] = {a[i].x, a[i].y, a[i].z, a[i].w};
            #pragma unroll
            for (int kk = 0; kk < 4; kk++) {
                float bv[4] = {b[kk].x, b[kk].y, b[kk].z, b[kk].w};
                #pragma unroll
                for (int j = 0; j < 4; j++) acc[i][j] += av[kk] * bv[j];
            }
        }
    }
    #pragma unroll
    for (int i = 0; i < 4; i++)
        *(float4*)&C[(r0 + i) * 68 + c0] = make_float4(acc[i][0], acc[i][1], acc[i][2], acc[i][3]);
    __syncthreads();
}

// ---------------- 3) gather landmarks + u = row_softmax(nr @ nc^T) + colsum/smax ----------------
__global__ void __launch_bounds__(256) gather_u_k(const float* __restrict__ Q,
                                                  const float* __restrict__ K) {
    extern __shared__ float sm[];
    float* snr  = sm;             // [64 m][68]
    float* sncT = sm + 4352;      // [64 k][68]
    float* su   = sm + 8704;      // [64][68]
    int p = blockIdx.x, t = threadIdx.x;
    const int* idxK = g_idxK + p * Mm;
    const int* idxQ = g_idxQ + p * Mm;
    for (int e = t; e < 4096; e += 256) {
        int m = e >> 6, d = e & 63;
        float vnc = K[((size_t)p * Nn + idxK[m]) * Dd + d];
        float vnr = Q[((size_t)p * Nn + idxQ[m]) * Dd + d] * 0.125f;
        g_nc[p * 4096 + e] = vnc;
        g_nr[p * 4096 + e] = vnr;
        snr[m * 68 + d] = vnr;
        sncT[d * 68 + m] = vnc;
    }
    __syncthreads();
    mm64(su, snr, sncT, t);
    if (t < 64) {
        float mx = -FLT_MAX;
        for (int c = 0; c < 64; c++) mx = fmaxf(mx, su[t * 68 + c]);
        float s = 0.f;
        for (int c = 0; c < 64; c++) s += __expf(su[t * 68 + c] - mx);
        float inv = 1.f / s;
        for (int c = 0; c < 64; c++) {
            float v = __expf(su[t * 68 + c] - mx) * inv;
            su[t * 68 + c] = v;
            g_u[p * 4096 + t * 64 + c] = v;
        }
    }
    __syncthreads();
    if (t < 64) {
        float cs = 0.f;
        for (int i = 0; i < 64; i++) cs += su[i * 68 + t];
        atomicMax((int*)&g_smax, __float_as_int(cs));
    }
}
#define GU_SMEM_BYTES (3 * 4352 * 4)

// ---------------- 4) flash RV (fp16x3, separate V buffer, 3 syncs/nt) ----------------
__global__ void __launch_bounds__(256) flash_rv_k(const float* __restrict__ K,
                                                  const float* __restrict__ V) {
    extern __shared__ uint32_t smu[];
    uint32_t* AsH = smu;            // nr split [64 m][HSTR]
    uint32_t* AsL = smu + 2304;
    uint32_t* PsH = smu + 4608;     // P split  [64 m][HSTR]
    uint32_t* PsL = smu + 6912;
    uint32_t* KbH = smu + 9216;     // K tile   [64 n][HSTR]
    uint32_t* KbL = smu + 11520;
    uint32_t* VbH = smu + 13824;    // V tile   [64 n][HSTR]
    uint32_t* VbL = smu + 16128;
    float*    red = (float*)(smu + 9216);   // aliases Kb (dead after the nt loop)
    int p  = blockIdx.x >> 3;
    int ch = blockIdx.x & 7;
    int t = threadIdx.x;
    for (int e = t; e < 2048; e += 256) {
        int m = e >> 5, kp = e & 31;
        float2 v = *(const float2*)&g_nr[p * 4096 + m * 64 + 2 * kp];
        h2split(v.x, v.y, AsH[m * HSTR + kp], AsL[m * HSTR + kp]);
    }
    const float* Kp = K + (size_t)p * Nn * Dd;
    const float* Vp = V + (size_t)p * Nn * Dd;
    int w = t >> 5, lane = t & 31, g = lane >> 2, tg = lane & 3;
    int mt = w & 3, nh = w >> 2;
    int r0 = mt * 16 + g;
    int lrow = lane & 15;
    uint32_t vbH = (uint32_t)__cvta_generic_to_shared(VbH);
    uint32_t vbL = (uint32_t)__cvta_generic_to_shared(VbL);
    float dRV[4][4] = {};
    float rs0 = 0.f, rs1 = 0.f;
    for (int nt = 0; nt < 8; nt++) {
        int nb = ch * 512 + nt * 64;
        __syncthreads();                        // prior RV-MMA (Ps,Vb reads) done; Kb long free
        // K+V fill in ONE phase: plain strided loops, no register staging (R10/R12 lesson).
        for (int e = t; e < 2048; e += 256) {
            int n = e >> 5, kp = e & 31;
            float2 kv = *(const float2*)&Kp[(size_t)(nb + n) * Dd + 2 * kp];
            float2 vv = *(const float2*)&Vp[(size_t)(nb + n) * Dd + 2 * kp];
            h2split(kv.x, kv.y, KbH[n * HSTR + kp], KbL[n * HSTR + kp]);
            h2split(vv.x, vv.y, VbH[n * HSTR + kp], VbL[n * HSTR + kp]);
        }
        __syncthreads();                        // tiles visible
        // S = nr @ K^T
        float dS[4][4] = {};
        #pragma unroll
        for (int ks = 0; ks < 4; ks++) {
            int kp0 = 8 * ks + tg;
            uint32_t ah[4], al[4];
            afrag(AsH, AsL, r0, kp0, ah, al);
            #pragma unroll
            for (int j = 0; j < 4; j++) {
                int c = nh * 32 + j * 8 + g;
                mma3(dS[j], ah, al,
                     KbH[c * HSTR + kp0], KbH[c * HSTR + kp0 + 4],
                     KbL[c * HSTR + kp0], KbL[c * HSTR + kp0 + 4]);
            }
        }
        // P = exp(S) (unnormalized; |S| small), rowsums, split-store (warp-private rows)
        #pragma unroll
        for (int j = 0; j < 4; j++) {
            int np = nh * 16 + j * 4 + tg;
            float e00 = __expf(dS[j][0]), e01 = __expf(dS[j][1]);
            float e10 = __expf(dS[j][2]), e11 = __expf(dS[j][3]);
            rs0 += e00 + e01; rs1 += e10 + e11;
            h2split(e00, e01, PsH[r0 * HSTR + np], PsL[r0 * HSTR + np]);
            h2split(e10, e11, PsH[(r0 + 8) * HSTR + np], PsL[(r0 + 8) * HSTR + np]);
        }
        __syncthreads();                        // P visible across nh-partner warps
        // RV += P @ V  (B frag via ldmatrix.trans on V's [k=n][d] rows)
        #pragma unroll
        for (int ks = 0; ks < 4; ks++) {
            int kp0 = 8 * ks + tg;
            uint32_t ah[4], al[4];
            afrag(PsH, PsL, r0, kp0, ah, al);
            int krow = 16 * ks + lrow;
            #pragma unroll
            for (int j = 0; j < 4; j++) {
                uint32_t off = (uint32_t)((krow * HSTR + nh * 16 + j * 4) * 4);
                uint32_t bh0, bh1, bl0, bl1;
                ldsm2t(bh0, bh1, vbH + off);
                ldsm2t(bl0, bl1, vbL + off);
                mma3(dRV[j], ah, al, bh0, bh1, bl0, bl1);
            }
        }
    }
    #pragma unroll
    for (int o = 1; o <= 2; o <<= 1) {
        rs0 += __shfl_xor_sync(0xffffffffu, rs0, o);
        rs1 += __shfl_xor_sync(0xffffffffu, rs1, o);
    }
    __syncthreads();                            // all MMA smem reads done; red may alias Kb
    if (tg == 0) { red[nh * 64 + r0] = rs0; red[nh * 64 + r0 + 8] = rs1; }
    __syncthreads();
    if (t < 64) g_rss[(p * KSPLIT + ch) * 64 + t] = red[t] + red[64 + t];
    float* out = g_rvp + ((size_t)blockIdx.x << 12);
    #pragma unroll
    for (int j = 0; j < 4; j++) {
        int cb = nh * 32 + j * 8 + 2 * tg;
        *(float2*)&out[r0 * 64 + cb]       = make_float2(dRV[j][0], dRV[j][1]);
        *(float2*)&out[(r0 + 8) * 64 + cb] = make_float2(dRV[j][2], dRV[j][3]);
    }
}
#define FLASH_SMEM_BYTES (18432 * 4)

// ---------------- 5) Newton-Schulz (+ fused RV merge) + W = Vinv @ RV ----------------
__global__ void __launch_bounds__(256) newton_k() {
    extern __shared__ float sm[];
    float* sKm  = sm;
    float* sV   = sm + 4352;
    float* sA   = sm + 8704;
    float* sT1  = sm + 13056;
    float* sT2  = sm + 17408;
    float* sden = sm + 21760;
    int p = blockIdx.x;
    int t = threadIdx.x;
    if (t < 64) {
        float den = 0.f;
        #pragma unroll
        for (int ch = 0; ch < KSPLIT; ch++) den += g_rss[(p * KSPLIT + ch) * 64 + t];
        sden[t] = 1.f / den;
    }
    for (int e = t; e < 4096; e += 256) {
        int r = e >> 6, c = e & 63;
        sKm[r * 68 + c] = g_u[p * 4096 + e];
    }
    __syncthreads();
    float invs = 1.f / __int_as_float((int)g_smax);
    for (int e = t; e < 4096; e += 256) {
        int r = e >> 6, c = e & 63;
        sV[r * 68 + c] = sKm[c * 68 + r] * invs;
    }
    __syncthreads();
    for (int it = 0; it < 6; it++) {
        mm64(sA, sKm, sV, t);
        for (int e = t; e < 4096; e += 256) {
            int r = e >> 6, c = e & 63;
            sT1[r * 68 + c] = (r == c ? 7.f : 0.f) - sA[r * 68 + c];
        }
        __syncthreads();
        mm64(sT2, sA, sT1, t);
        for (int e = t; e < 4096; e += 256) {
            int r = e >> 6, c = e & 63;
            sT1[r * 68 + c] = (r == c ? 15.f : 0.f) - sT2[r * 68 + c];
        }
        __syncthreads();
        mm64(sT2, sA, sT1, t);
        for (int e = t; e < 4096; e += 256) {
            int r = e >> 6, c = e & 63;
            sT1[r * 68 + c] = (r == c ? 13.f : 0.f) - sT2[r * 68 + c];
        }
        __syncthreads();
        mm64(sT2, sV, sT1, t);
        for (int e = t; e < 4096; e += 256) {
            int r = e >> 6, c = e & 63;
            sV[r * 68 + c] = 0.25f * sT2[r * 68 + c];
        }
        __syncthreads();
    }
    for (int e = t; e < 4096; e += 256) {
        int r = e >> 6, c = e & 63;
        float s = 0.f;
        #pragma unroll
        for (int ch = 0; ch < KSPLIT; ch++) s += g_rvp[((size_t)(p * KSPLIT + ch) << 12) + e];
        sT1[r * 68 + c] = s * sden[r];
    }
    __syncthreads();
    mm64(sT2, sV, sT1, t);
    for (int e = t; e < 4096; e += 256) {
        int r = e >> 6, c = e & 63;
        g_w[p * 4096 + e] = sT2[r * 68 + c];
    }
}
#define NEWTON_SMEM_BYTES ((5 * 4352 + 64) * 4)

// ---------------- 6) fused X (fp16x3): c -> softmax -> @W -> out ----------------
__global__ void __launch_bounds__(256) x_fused_k(const float* __restrict__ Q,
                                                 float* __restrict__ out) {
    extern __shared__ uint32_t smu[];
    uint32_t* AsH = smu;            // Q tile, then k1 tile [128][HSTR]
    uint32_t* AsL = smu + 4608;
    uint32_t* BsH = smu + 9216;     // nc, then W [64][HSTR]
    uint32_t* BsL = smu + 11520;
    int p  = blockIdx.x >> 5;
    int n0 = (blockIdx.x & 31) * 128;
    int t = threadIdx.x;
    const float* Ag = Q + ((size_t)p * Nn + n0) * Dd;
    for (int e = t; e < 4096; e += 256) {
        int m = e >> 5, kp = e & 31;
        float2 v = *(const float2*)&Ag[m * 64 + 2 * kp];
        h2split(v.x * 0.125f, v.y * 0.125f, AsH[m * HSTR + kp], AsL[m * HSTR + kp]);
    }
    const float* Bg = g_nc + (size_t)p * Mm * Dd;
    for (int e = t; e < 2048; e += 256) {
        int c = e >> 5, kp = e & 31;
        float2 v = *(const float2*)&Bg[c * 64 + 2 * kp];
        h2split(v.x, v.y, BsH[c * HSTR + kp], BsL[c * HSTR + kp]);
    }
    __syncthreads();
    int w = t >> 5, lane = t & 31, g = lane >> 2, tg = lane & 3;
    int r0 = w * 16 + g;
    int lrow = lane & 15;
    // GEMM 1: c = Qs @ nc^T
    float d[8][4] = {};
    #pragma unroll
    for (int ks = 0; ks < 4; ks++) {
        int kp0 = 8 * ks + tg;
        uint32_t ah[4], al[4];
        afrag(AsH, AsL, r0, kp0, ah, al);
        #pragma unroll
        for (int j = 0; j < 8; j++) {
            int c = j * 8 + g;
            mma3(d[j], ah, al,
                 BsH[c * HSTR + kp0], BsH[c * HSTR + kp0 + 4],
                 BsL[c * HSTR + kp0], BsL[c * HSTR + kp0 + 4]);
        }
    }
    // exact row softmax over the 4-lane group
    float mx0 = -FLT_MAX, mx1 = -FLT_MAX;
    #pragma unroll
    for (int j = 0; j < 8; j++) {
        mx0 = fmaxf(mx0, fmaxf(d[j][0], d[j][1]));
        mx1 = fmaxf(mx1, fmaxf(d[j][2], d[j][3]));
    }
    #pragma unroll
    for (int o = 1; o <= 2; o <<= 1) {
        mx0 = fmaxf(mx0, __shfl_xor_sync(0xffffffffu, mx0, o));
        mx1 = fmaxf(mx1, __shfl_xor_sync(0xffffffffu, mx1, o));
    }
    float s0 = 0.f, s1 = 0.f;
    #pragma unroll
    for (int j = 0; j < 8; j++) {
        d[j][0] = __expf(d[j][0] - mx0); d[j][1] = __expf(d[j][1] - mx0);
        d[j][2] = __expf(d[j][2] - mx1); d[j][3] = __expf(d[j][3] - mx1);
        s0 += d[j][0] + d[j][1];
        s1 += d[j][2] + d[j][3];
    }
    #pragma unroll
    for (int o = 1; o <= 2; o <<= 1) {
        s0 += __shfl_xor_sync(0xffffffffu, s0, o);
        s1 += __shfl_xor_sync(0xffffffffu, s1, o);
    }
    float i0 = 1.f / s0, i1 = 1.f / s1;
    // store k1 split into As (warp-private rows; n-adjacent pairs)
    #pragma unroll
    for (int j = 0; j < 8; j++) {
        int np = j * 4 + tg;
        h2split(d[j][0] * i0, d[j][1] * i0, AsH[r0 * HSTR + np], AsL[r0 * HSTR + np]);
        h2split(d[j][2] * i1, d[j][3] * i1, AsH[(r0 + 8) * HSTR + np], AsL[(r0 + 8) * HSTR + np]);
    }
    // reuse d as the GEMM-2 accumulator (register save; no forced occupancy)
    #pragma unroll
    for (int j = 0; j < 8; j++)
        #pragma unroll
        for (int q = 0; q < 4; q++) d[j][q] = 0.f;
    __syncthreads();                 // all warps done with Bs(nc); k1 stores visible
    const float* Wg = g_w + (size_t)p * Mm * Dd;
    for (int e = t; e < 2048; e += 256) {
        int k = e >> 5, dp = e & 31;
        float2 v = *(const float2*)&Wg[k * 64 + 2 * dp];
        h2split(v.x, v.y, BsH[k * HSTR + dp], BsL[k * HSTR + dp]);
    }
    __syncthreads();
    uint32_t wbH = (uint32_t)__cvta_generic_to_shared(BsH);
    uint32_t wbL = (uint32_t)__cvta_generic_to_shared(BsL);
    // GEMM 2: X = k1 @ W
    #pragma unroll
    for (int ks = 0; ks < 4; ks++) {
        int kp0 = 8 * ks + tg;
        uint32_t ah[4], al[4];
        afrag(AsH, AsL, r0, kp0, ah, al);
        int krow = 16 * ks + lrow;
        #pragma unroll
        for (int j = 0; j < 8; j++) {
            uint32_t off = (uint32_t)((krow * HSTR + j * 4) * 4);
            uint32_t bh0, bh1, bl0, bl1;
            ldsm2t(bh0, bh1, wbH + off);
            ldsm2t(bl0, bl1, wbL + off);
            mma3(d[j], ah, al, bh0, bh1, bl0, bl1);
        }
    }
    size_t row0 = (size_t)p * Nn + n0 + r0;
    #pragma unroll
    for (int j = 0; j < 8; j++) {
        int c0 = j * 8 + 2 * tg;
        *(float2*)&out[row0 * Dd + c0]       = make_float2(d[j][0], d[j][1]);
        *(float2*)&out[(row0 + 8) * Dd + c0] = make_float2(d[j][2], d[j][3]);
    }
}
#define XF_SMEM_BYTES (13824 * 4)

// ---------------- launch ----------------
extern "C" void kernel_launch(void* const* d_in, const int* in_sizes, int n_in,
                              void* d_out, int out_size) {
    const float* Q = (const float*)d_in[0];
    const float* K = (const float*)d_in[1];
    const float* V = (const float*)d_in[2];
    float* out = (float*)d_out;

    cudaFuncSetAttribute(gather_u_k, cudaFuncAttributeMaxDynamicSharedMemorySize, GU_SMEM_BYTES);
    cudaFuncSetAttribute(flash_rv_k, cudaFuncAttributeMaxDynamicSharedMemorySize, FLASH_SMEM_BYTES);
    cudaFuncSetAttribute(newton_k,   cudaFuncAttributeMaxDynamicSharedMemorySize, NEWTON_SMEM_BYTES);
    cudaFuncSetAttribute(x_fused_k,  cudaFuncAttributeMaxDynamicSharedMemorySize, XF_SMEM_BYTES);

    scores_k  <<<Pp * Nn / 8, dim3(32, 8)>>>(Q, K);
    topk_k    <<<2 * Pp, 256>>>();
    gather_u_k<<<Pp, 256, GU_SMEM_BYTES>>>(Q, K);
    flash_rv_k<<<Pp * KSPLIT, 256, FLASH_SMEM_BYTES>>>(K, V);
    newton_k  <<<Pp, 256, NEWTON_SMEM_BYTES>>>();
    x_fused_k <<<Pp * 32, 256, XF_SMEM_BYTES>>>(Q, out);
}

// round 15
// speedup vs baseline: 1.1677x; 1.1270x over previous
#include <cuda_runtime.h>
#include <cuda_fp16.h>
#include <cfloat>
#include <cstdint>

// Problem constants
#define Bb 8
#define Hh 8
#define Nn 4096
#define Dd 64
#define Mm 64
#define Pp (Bb*Hh)        // 64 (b,h) pairs
#define KSPLIT 8

#define HSTR 36           // half2-word stride: frag reads land on banks 4g+tg (conflict-free)

// ---------------- scratch (device globals) ----------------
__device__ float g_sK [Pp*Nn];
__device__ float g_sQ [Pp*Nn];
__device__ int   g_idxK[Pp*Mm];
__device__ int   g_idxQ[Pp*Mm];
__device__ float g_nc [Pp*Mm*Dd];         // column landmarks (rows of K)
__device__ float g_nr [Pp*Mm*Dd];         // row landmarks (rows of Qs, pre-scaled 1/8)
__device__ float g_u  [Pp*Mm*Mm];
__device__ float g_rvp[(size_t)Pp*KSPLIT*Mm*Dd]; // unnormalized RV partials
__device__ float g_rss[Pp*KSPLIT*Mm];            // rowsum-of-exp partials
__device__ float g_w  [Pp*Mm*Dd];
__device__ unsigned int g_smax;

// ---------------- fp16 split helpers ----------------
__device__ __forceinline__ void h2split(float x, float y, uint32_t& h, uint32_t& l) {
    __half hx = __float2half_rn(x), hy = __float2half_rn(y);
    float rx = x - __half2float(hx), ry = y - __half2float(hy);
    __half lx = __float2half_rn(rx), ly = __float2half_rn(ry);
    h = (uint32_t)__half_as_ushort(hx) | ((uint32_t)__half_as_ushort(hy) << 16);
    l = (uint32_t)__half_as_ushort(lx) | ((uint32_t)__half_as_ushort(ly) << 16);
}

__device__ __forceinline__ void mma_f16(float* d, uint32_t a0, uint32_t a1, uint32_t a2, uint32_t a3,
                                        uint32_t b0, uint32_t b1) {
    asm volatile(
        "mma.sync.aligned.m16n8k16.row.col.f32.f16.f16.f32 "
        "{%0,%1,%2,%3},{%4,%5,%6,%7},{%8,%9},{%0,%1,%2,%3};"
        : "+f"(d[0]), "+f"(d[1]), "+f"(d[2]), "+f"(d[3])
        : "r"(a0), "r"(a1), "r"(a2), "r"(a3), "r"(b0), "r"(b1));
}
// fp16x3: D += Ah*Bh + Ah*Bl + Al*Bh
__device__ __forceinline__ void mma3(float* d, const uint32_t* ah, const uint32_t* al,
                                     uint32_t bh0, uint32_t bh1, uint32_t bl0, uint32_t bl1) {
    mma_f16(d, ah[0], ah[1], ah[2], ah[3], bh0, bh1);
    mma_f16(d, ah[0], ah[1], ah[2], ah[3], bl0, bl1);
    mma_f16(d, al[0], al[1], al[2], al[3], bh0, bh1);
}
__device__ __forceinline__ void ldsm2t(uint32_t& r0, uint32_t& r1, uint32_t saddr) {
    asm volatile("ldmatrix.sync.aligned.m8n8.x2.trans.shared.b16 {%0,%1}, [%2];"
                 : "=r"(r0), "=r"(r1) : "r"(saddr));
}
__device__ __forceinline__ void afrag(const uint32_t* H, const uint32_t* L, int r0, int kp0,
                                      uint32_t* ah, uint32_t* al) {
    ah[0] = H[r0 * HSTR + kp0];       al[0] = L[r0 * HSTR + kp0];
    ah[1] = H[(r0 + 8) * HSTR + kp0]; al[1] = L[(r0 + 8) * HSTR + kp0];
    ah[2] = H[r0 * HSTR + kp0 + 4];       al[2] = L[r0 * HSTR + kp0 + 4];
    ah[3] = H[(r0 + 8) * HSTR + kp0 + 4]; al[3] = L[(r0 + 8) * HSTR + kp0 + 4];
}

// ---------------- 1) scores ----------------
__global__ void scores_k(const float* __restrict__ Q, const float* __restrict__ K) {
    if (blockIdx.x == 0 && threadIdx.x == 0 && threadIdx.y == 0) g_smax = 0u;
    int row = blockIdx.x * 8 + threadIdx.y;
    if (row >= Pp * Nn) return;
    int lane = threadIdx.x;
    const float* q = Q + (size_t)row * Dd;
    const float* k = K + (size_t)row * Dd;
    float sq = q[lane] + q[lane + 32];
    float sk = k[lane] + k[lane + 32];
    #pragma unroll
    for (int o = 16; o; o >>= 1) {
        sq += __shfl_xor_sync(0xffffffffu, sq, o);
        sk += __shfl_xor_sync(0xffffffffu, sk, o);
    }
    if (lane == 0) { g_sQ[row] = sq; g_sK[row] = sk; }
}

// ---------------- 2) top-64 via 4-pass radix select ----------------
__global__ void __launch_bounds__(256) topk_k() {
    __shared__ unsigned key[Nn];
    __shared__ unsigned hist[256];
    __shared__ unsigned sh_pref;
    __shared__ int      sh_krem;
    __shared__ unsigned sh_cnt, sh_tie;
    __shared__ int      tiebuf[64];
    int p   = blockIdx.x & (Pp - 1);
    bool isK = blockIdx.x < Pp;
    const float* src = (isK ? g_sK : g_sQ) + (size_t)p * Nn;
    int* dst = (isK ? g_idxK : g_idxQ) + p * Mm;
    int t = threadIdx.x;
    for (int i = t; i < Nn; i += 256) {
        unsigned u = __float_as_uint(src[i]);
        key[i] = u ^ ((unsigned)((int)u >> 31) | 0x80000000u);
    }
    if (t == 0) { sh_pref = 0u; sh_krem = Mm; sh_cnt = 0u; sh_tie = 0u; }
    __syncthreads();
    #pragma unroll
    for (int b = 3; b >= 0; b--) {
        hist[t] = 0u;
        __syncthreads();
        unsigned maskHi = (b == 3) ? 0u : (0xFFFFFFFFu << ((b + 1) * 8));
        unsigned pref = sh_pref;
        for (int i = t; i < Nn; i += 256) {
            unsigned k = key[i];
            if ((k & maskHi) == pref)
                atomicAdd(&hist[(k >> (b * 8)) & 0xFFu], 1u);
        }
        __syncthreads();
        if (t == 0) {
            int krem = sh_krem, acc = 0, bsel = 0;
            for (int bin = 255; bin >= 0; bin--) {
                int c = (int)hist[bin];
                if (acc + c >= krem) { bsel = bin; break; }
                acc += c;
            }
            sh_krem = krem - acc;
            sh_pref = sh_pref | ((unsigned)bsel << (b * 8));
        }
        __syncthreads();
    }
    unsigned T = sh_pref;
    for (int i = t; i < Nn; i += 256) {
        unsigned k = key[i];
        if (k > T) {
            unsigned pos = atomicAdd(&sh_cnt, 1u);
            dst[pos] = i;
        } else if (k == T) {
            unsigned tp = atomicAdd(&sh_tie, 1u);
            if (tp < 64u) tiebuf[tp] = i;
        }
    }
    __syncthreads();
    if (t == 0) {
        int n = (int)min(sh_tie, 64u);
        for (int i = 1; i < n; i++) {
            int v = tiebuf[i], j = i - 1;
            while (j >= 0 && tiebuf[j] > v) { tiebuf[j + 1] = tiebuf[j]; j--; }
            tiebuf[j + 1] = v;
        }
        int base = (int)sh_cnt, krem = sh_krem;
        for (int j = 0; j < krem; j++) dst[base + j] = tiebuf[j];
    }
}

// ---------------- float4 64x64x64 smem GEMM, 256 threads (stride 68): C = A @ B ----------------
__device__ __forceinline__ void mm64(float* C, const float* A, const float* B, int t) {
    int tx = t & 15, ty = t >> 4, r0 = ty * 4, c0 = tx * 4;
    float acc[4][4] = {};
    #pragma unroll
    for (int k0 = 0; k0 < 64; k0 += 4) {
        float4 a[4], b[4];
        #pragma unroll
        for (int i = 0; i < 4; i++) a[i] = *(const float4*)&A[(r0 + i) * 68 + k0];
        #pragma unroll
        for (int kk = 0; kk < 4; kk++) b[kk] = *(const float4*)&B[(k0 + kk) * 68 + c0];
        #pragma unroll
        for (int i = 0; i < 4; i++) {
            float av[4] = {a[i].x, a[i].y, a[i].z, a[i].w};
            #pragma unroll
            for (int kk = 0; kk < 4; kk++) {
                float bv[4] = {b[kk].x, b[kk].y, b[kk].z, b[kk].w};
                #pragma unroll
                for (int j = 0; j < 4; j++) acc[i][j] += av[kk] * bv[j];
            }
        }
    }
    #pragma unroll
    for (int i = 0; i < 4; i++)
        *(float4*)&C[(r0 + i) * 68 + c0] = make_float4(acc[i][0], acc[i][1], acc[i][2], acc[i][3]);
    __syncthreads();
}

// ---------------- 3) gather landmarks + u = row_softmax(nr @ nc^T) + colsum/smax ----------------
__global__ void __launch_bounds__(256) gather_u_k(const float* __restrict__ Q,
                                                  const float* __restrict__ K) {
    extern __shared__ float sm[];
    float* snr  = sm;             // [64 m][68]
    float* sncT = sm + 4352;      // [64 k][68]
    float* su   = sm + 8704;      // [64][68]
    int p = blockIdx.x, t = threadIdx.x;
    const int* idxK = g_idxK + p * Mm;
    const int* idxQ = g_idxQ + p * Mm;
    for (int e = t; e < 4096; e += 256) {
        int m = e >> 6, d = e & 63;
        float vnc = K[((size_t)p * Nn + idxK[m]) * Dd + d];
        float vnr = Q[((size_t)p * Nn + idxQ[m]) * Dd + d] * 0.125f;
        g_nc[p * 4096 + e] = vnc;
        g_nr[p * 4096 + e] = vnr;
        snr[m * 68 + d] = vnr;
        sncT[d * 68 + m] = vnc;
    }
    __syncthreads();
    mm64(su, snr, sncT, t);
    if (t < 64) {
        float mx = -FLT_MAX;
        for (int c = 0; c < 64; c++) mx = fmaxf(mx, su[t * 68 + c]);
        float s = 0.f;
        for (int c = 0; c < 64; c++) s += __expf(su[t * 68 + c] - mx);
        float inv = 1.f / s;
        for (int c = 0; c < 64; c++) {
            float v = __expf(su[t * 68 + c] - mx) * inv;
            su[t * 68 + c] = v;
            g_u[p * 4096 + t * 64 + c] = v;
        }
    }
    __syncthreads();
    if (t < 64) {
        float cs = 0.f;
        for (int i = 0; i < 64; i++) cs += su[i * 68 + t];
        atomicMax((int*)&g_smax, __float_as_int(cs));
    }
}
#define GU_SMEM_BYTES (3 * 4352 * 4)

// ---------------- 4) flash RV (fp16x3, exact R9 structure): Σ exp(nr@K^T)·V over an N-chunk ----------------
__global__ void __launch_bounds__(256) flash_rv_k(const float* __restrict__ K,
                                                  const float* __restrict__ V) {
    extern __shared__ uint32_t smu[];
    uint32_t* AsH = smu;            // nr split [64 m][HSTR]
    uint32_t* AsL = smu + 2304;
    uint32_t* PsH = smu + 4608;     // P split  [64 m][HSTR]
    uint32_t* PsL = smu + 6912;
    uint32_t* BsH = smu + 9216;     // K then V [64 rows][HSTR]
    uint32_t* BsL = smu + 11520;
    float*    red = (float*)(smu + 13824);
    int p  = blockIdx.x >> 3;
    int ch = blockIdx.x & 7;
    int t = threadIdx.x;
    for (int e = t; e < 2048; e += 256) {
        int m = e >> 5, kp = e & 31;
        float2 v = *(const float2*)&g_nr[p * 4096 + m * 64 + 2 * kp];
        h2split(v.x, v.y, AsH[m * HSTR + kp], AsL[m * HSTR + kp]);
    }
    const float* Kp = K + (size_t)p * Nn * Dd;
    const float* Vp = V + (size_t)p * Nn * Dd;
    int w = t >> 5, lane = t & 31, g = lane >> 2, tg = lane & 3;
    int mt = w & 3, nh = w >> 2;
    int r0 = mt * 16 + g;
    int lrow = lane & 15;
    uint32_t vbH = (uint32_t)__cvta_generic_to_shared(BsH);
    uint32_t vbL = (uint32_t)__cvta_generic_to_shared(BsL);
    float dRV[4][4] = {};
    float rs0 = 0.f, rs1 = 0.f;
    for (int nt = 0; nt < 8; nt++) {
        int nb = ch * 512 + nt * 64;
        __syncthreads();                        // prior RV-MMA done before Bs overwrite
        for (int e = t; e < 2048; e += 256) {   // Bs = K rows: [n][k-pairs]
            int n = e >> 5, kp = e & 31;
            float2 v = *(const float2*)&Kp[(size_t)(nb + n) * Dd + 2 * kp];
            h2split(v.x, v.y, BsH[n * HSTR + kp], BsL[n * HSTR + kp]);
        }
        __syncthreads();
        float dS[4][4] = {};
        #pragma unroll
        for (int ks = 0; ks < 4; ks++) {
            int kp0 = 8 * ks + tg;
            uint32_t ah[4], al[4];
            afrag(AsH, AsL, r0, kp0, ah, al);
            #pragma unroll
            for (int j = 0; j < 4; j++) {
                int c = nh * 32 + j * 8 + g;
                mma3(dS[j], ah, al,
                     BsH[c * HSTR + kp0], BsH[c * HSTR + kp0 + 4],
                     BsL[c * HSTR + kp0], BsL[c * HSTR + kp0 + 4]);
            }
        }
        #pragma unroll
        for (int j = 0; j < 4; j++) {
            int np = nh * 16 + j * 4 + tg;
            float e00 = __expf(dS[j][0]), e01 = __expf(dS[j][1]);
            float e10 = __expf(dS[j][2]), e11 = __expf(dS[j][3]);
            rs0 += e00 + e01; rs1 += e10 + e11;
            h2split(e00, e01, PsH[r0 * HSTR + np], PsL[r0 * HSTR + np]);
            h2split(e10, e11, PsH[(r0 + 8) * HSTR + np], PsL[(r0 + 8) * HSTR + np]);
        }
        __syncthreads();                        // P complete; Bs free
        for (int e = t; e < 2048; e += 256) {   // Bs = V rows: [n][d-pairs]
            int n = e >> 5, dp = e & 31;
            float2 v = *(const float2*)&Vp[(size_t)(nb + n) * Dd + 2 * dp];
            h2split(v.x, v.y, BsH[n * HSTR + dp], BsL[n * HSTR + dp]);
        }
        __syncthreads();
        #pragma unroll
        for (int ks = 0; ks < 4; ks++) {
            int kp0 = 8 * ks + tg;
            uint32_t ah[4], al[4];
            afrag(PsH, PsL, r0, kp0, ah, al);
            int krow = 16 * ks + lrow;
            #pragma unroll
            for (int j = 0; j < 4; j++) {
                uint32_t off = (uint32_t)((krow * HSTR + nh * 16 + j * 4) * 4);
                uint32_t bh0, bh1, bl0, bl1;
                ldsm2t(bh0, bh1, vbH + off);
                ldsm2t(bl0, bl1, vbL + off);
                mma3(dRV[j], ah, al, bh0, bh1, bl0, bl1);
            }
        }
    }
    #pragma unroll
    for (int o = 1; o <= 2; o <<= 1) {
        rs0 += __shfl_xor_sync(0xffffffffu, rs0, o);
        rs1 += __shfl_xor_sync(0xffffffffu, rs1, o);
    }
    __syncthreads();
    if (tg == 0) { red[nh * 64 + r0] = rs0; red[nh * 64 + r0 + 8] = rs1; }
    __syncthreads();
    if (t < 64) g_rss[(p * KSPLIT + ch) * 64 + t] = red[t] + red[64 + t];
    float* out = g_rvp + ((size_t)blockIdx.x << 12);
    #pragma unroll
    for (int j = 0; j < 4; j++) {
        int cb = nh * 32 + j * 8 + 2 * tg;
        *(float2*)&out[r0 * 64 + cb]       = make_float2(dRV[j][0], dRV[j][1]);
        *(float2*)&out[(r0 + 8) * 64 + cb] = make_float2(dRV[j][2], dRV[j][3]);
    }
}
#define FLASH_SMEM_BYTES ((13824 + 128) * 4)

// ---------------- 5) Newton-Schulz on tensor cores (fp16x3) + fused RV merge + W = Vinv @ RV ----------------
// Forms: A-form split of M: [r][kp] packs (M[r][2kp], M[r][2kp+1]).
//        B-form split of M (as MMA B operand): [n][kp] packs (M[2kp][n], M[2kp+1][n]).
// MMA computes C = Aop @ Bop with Aop in A-form, Bop in B-form (same fragment
// conventions as flash_rv's S-GEMM). C written fp32 [64][68].

// one 64x64x64 fp16x3 MMA GEMM; fragments per warp: rows mt*16..+16, cols nh*32..+32
__device__ __forceinline__ void mmaC64(float* C,
                                       const uint32_t* AH, const uint32_t* AL,
                                       const uint32_t* BH, const uint32_t* BL,
                                       int r0, int nh, int g, int tg) {
    float dC[4][4] = {};
    #pragma unroll
    for (int ks = 0; ks < 4; ks++) {
        int kp0 = 8 * ks + tg;
        uint32_t ah[4], al[4];
        afrag(AH, AL, r0, kp0, ah, al);
        #pragma unroll
        for (int j = 0; j < 4; j++) {
            int c = nh * 32 + j * 8 + g;
            mma3(dC[j], ah, al,
                 BH[c * HSTR + kp0], BH[c * HSTR + kp0 + 4],
                 BL[c * HSTR + kp0], BL[c * HSTR + kp0 + 4]);
        }
    }
    #pragma unroll
    for (int j = 0; j < 4; j++) {
        int cb = nh * 32 + j * 8 + 2 * tg;
        *(float2*)&C[r0 * 68 + cb]       = make_float2(dC[j][0], dC[j][1]);
        *(float2*)&C[(r0 + 8) * 68 + cb] = make_float2(dC[j][2], dC[j][3]);
    }
}
// A-form split of scale*C
__device__ __forceinline__ void splitA(uint32_t* AH, uint32_t* AL, const float* C,
                                       float scale, int t) {
    for (int e = t; e < 2048; e += 256) {
        int m = e >> 5, kp = e & 31;
        float2 v = *(const float2*)&C[m * 68 + 2 * kp];
        h2split(v.x * scale, v.y * scale, AH[m * HSTR + kp], AL[m * HSTR + kp]);
    }
}
// B-form split of (coef*I + scale*C)
__device__ __forceinline__ void splitB(uint32_t* BH, uint32_t* BL, const float* C,
                                       float coef, float scale, int t) {
    for (int e = t; e < 2048; e += 256) {
        int n = e & 63, kpr = e >> 6;       // n fast within warp -> conflict-free C reads
        int ra = 2 * kpr, rb = ra + 1;
        float v0 = (ra == n ? coef : 0.f) + scale * C[ra * 68 + n];
        float v1 = (rb == n ? coef : 0.f) + scale * C[rb * 68 + n];
        h2split(v0, v1, BH[n * HSTR + kpr], BL[n * HSTR + kpr]);
    }
}

__global__ void __launch_bounds__(256) newton_k() {
    extern __shared__ uint32_t smu[];
    uint32_t* KmH = smu;              // A-form Km (const)
    uint32_t* KmL = smu + 2304;
    uint32_t* VAH = smu + 4608;       // A-form V
    uint32_t* VAL = smu + 6912;
    uint32_t* VBH = smu + 9216;       // B-form V
    uint32_t* VBL = smu + 11520;
    uint32_t* TBH = smu + 13824;      // B-form T (polynomial operand; reused for RV at end)
    uint32_t* TBL = smu + 16128;
    uint32_t* XAH = smu + 18432;      // A-form KV
    uint32_t* XAL = smu + 20736;
    float*    C   = (float*)(smu + 23040);        // [64][68] fp32
    float*    sden= (float*)(smu + 23040 + 4352); // [64]
    int p = blockIdx.x, t = threadIdx.x;
    if (t < 64) {
        float den = 0.f;
        #pragma unroll
        for (int ch = 0; ch < KSPLIT; ch++) den += g_rss[(p * KSPLIT + ch) * 64 + t];
        sden[t] = 1.f / den;
    }
    float invs = 1.f / __int_as_float((int)g_smax);
    const float* up = g_u + p * 4096;
    // Km A-form;  V0 = Km^T*invs -> V0 B-form[n][kp] = (Km[n][2kp],Km[n][2kp+1])*invs (row-major reads)
    for (int e = t; e < 2048; e += 256) {
        int m = e >> 5, kp = e & 31;
        float2 v = *(const float2*)&up[m * 64 + 2 * kp];
        h2split(v.x, v.y, KmH[m * HSTR + kp], KmL[m * HSTR + kp]);
        h2split(v.x * invs, v.y * invs, VBH[m * HSTR + kp], VBL[m * HSTR + kp]);
    }
    // V0 A-form[r][kp] = (Km[2kp][r], Km[2kp+1][r])*invs (transposed reads, r fast -> coalesced)
    for (int e = t; e < 2048; e += 256) {
        int r = e & 63, kp = e >> 6;
        float a = up[(2 * kp) * 64 + r] * invs;
        float b = up[(2 * kp + 1) * 64 + r] * invs;
        h2split(a, b, VAH[r * HSTR + kp], VAL[r * HSTR + kp]);
    }
    __syncthreads();
    int w = t >> 5, lane = t & 31, g = lane >> 2, tg = lane & 3;
    int mt = w & 3, nh = w >> 2;
    int r0 = mt * 16 + g;
    for (int it = 0; it < 6; it++) {
        mmaC64(C, KmH, KmL, VBH, VBL, r0, nh, g, tg);   // C = KV = Km @ V
        __syncthreads();
        splitA(XAH, XAL, C, 1.0f, t);                   // XA = KV
        splitB(TBH, TBL, C, 7.f, -1.f, t);              // TB = 7I - KV
        __syncthreads();
        mmaC64(C, XAH, XAL, TBH, TBL, r0, nh, g, tg);   // C = KV @ (7I - KV)
        __syncthreads();
        splitB(TBH, TBL, C, 15.f, -1.f, t);             // TB = 15I - C
        __syncthreads();
        mmaC64(C, XAH, XAL, TBH, TBL, r0, nh, g, tg);   // C = KV @ (15I - ...)
        __syncthreads();
        splitB(TBH, TBL, C, 13.f, -1.f, t);             // TB = 13I - C
        __syncthreads();
        mmaC64(C, VAH, VAL, TBH, TBL, r0, nh, g, tg);   // C = V @ (13I - ...) = 4*Vnew
        __syncthreads();
        splitA(VAH, VAL, C, 0.25f, t);                  // V A-form
        splitB(VBH, VBL, C, 0.f, 0.25f, t);             // V B-form
        __syncthreads();
    }
    // RV B-form (merge split-K partials, normalize by rowsum) into TB
    for (int e = t; e < 2048; e += 256) {
        int n = e & 63, kpr = e >> 6;
        int ra = 2 * kpr, rb = ra + 1;
        float s0 = 0.f, s1 = 0.f;
        #pragma unroll
        for (int ch = 0; ch < KSPLIT; ch++) {
            const float* part = g_rvp + (((size_t)(p * KSPLIT + ch)) << 12);
            s0 += part[ra * 64 + n];
            s1 += part[rb * 64 + n];
        }
        h2split(s0 * sden[ra], s1 * sden[rb], TBH[n * HSTR + kpr], TBL[n * HSTR + kpr]);
    }
    __syncthreads();
    // W = Vinv @ RV  -> fragments straight to gmem
    {
        float dC[4][4] = {};
        #pragma unroll
        for (int ks = 0; ks < 4; ks++) {
            int kp0 = 8 * ks + tg;
            uint32_t ah[4], al[4];
            afrag(VAH, VAL, r0, kp0, ah, al);
            #pragma unroll
            for (int j = 0; j < 4; j++) {
                int c = nh * 32 + j * 8 + g;
                mma3(dC[j], ah, al,
                     TBH[c * HSTR + kp0], TBH[c * HSTR + kp0 + 4],
                     TBL[c * HSTR + kp0], TBL[c * HSTR + kp0 + 4]);
            }
        }
        float* Wp = g_w + p * 4096;
        #pragma unroll
        for (int j = 0; j < 4; j++) {
            int cb = nh * 32 + j * 8 + 2 * tg;
            *(float2*)&Wp[r0 * 64 + cb]       = make_float2(dC[j][0], dC[j][1]);
            *(float2*)&Wp[(r0 + 8) * 64 + cb] = make_float2(dC[j][2], dC[j][3]);
        }
    }
}
#define NEWTON_SMEM_BYTES ((23040 + 4352 + 64) * 4)

// ---------------- 6) fused X (fp16x3): c -> softmax -> @W -> out ----------------
__global__ void __launch_bounds__(256) x_fused_k(const float* __restrict__ Q,
                                                 float* __restrict__ out) {
    extern __shared__ uint32_t smu[];
    uint32_t* AsH = smu;            // Q tile, then k1 tile [128][HSTR]
    uint32_t* AsL = smu + 4608;
    uint32_t* BsH = smu + 9216;     // nc, then W [64][HSTR]
    uint32_t* BsL = smu + 11520;
    int p  = blockIdx.x >> 5;
    int n0 = (blockIdx.x & 31) * 128;
    int t = threadIdx.x;
    const float* Ag = Q + ((size_t)p * Nn + n0) * Dd;
    for (int e = t; e < 4096; e += 256) {
        int m = e >> 5, kp = e & 31;
        float2 v = *(const float2*)&Ag[m * 64 + 2 * kp];
        h2split(v.x * 0.125f, v.y * 0.125f, AsH[m * HSTR + kp], AsL[m * HSTR + kp]);
    }
    const float* Bg = g_nc + (size_t)p * Mm * Dd;
    for (int e = t; e < 2048; e += 256) {
        int c = e >> 5, kp = e & 31;
        float2 v = *(const float2*)&Bg[c * 64 + 2 * kp];
        h2split(v.x, v.y, BsH[c * HSTR + kp], BsL[c * HSTR + kp]);
    }
    __syncthreads();
    int w = t >> 5, lane = t & 31, g = lane >> 2, tg = lane & 3;
    int r0 = w * 16 + g;
    int lrow = lane & 15;
    // GEMM 1: c = Qs @ nc^T
    float d[8][4] = {};
    #pragma unroll
    for (int ks = 0; ks < 4; ks++) {
        int kp0 = 8 * ks + tg;
        uint32_t ah[4], al[4];
        afrag(AsH, AsL, r0, kp0, ah, al);
        #pragma unroll
        for (int j = 0; j < 8; j++) {
            int c = j * 8 + g;
            mma3(d[j], ah, al,
                 BsH[c * HSTR + kp0], BsH[c * HSTR + kp0 + 4],
                 BsL[c * HSTR + kp0], BsL[c * HSTR + kp0 + 4]);
        }
    }
    // exact row softmax over the 4-lane group
    float mx0 = -FLT_MAX, mx1 = -FLT_MAX;
    #pragma unroll
    for (int j = 0; j < 8; j++) {
        mx0 = fmaxf(mx0, fmaxf(d[j][0], d[j][1]));
        mx1 = fmaxf(mx1, fmaxf(d[j][2], d[j][3]));
    }
    #pragma unroll
    for (int o = 1; o <= 2; o <<= 1) {
        mx0 = fmaxf(mx0, __shfl_xor_sync(0xffffffffu, mx0, o));
        mx1 = fmaxf(mx1, __shfl_xor_sync(0xffffffffu, mx1, o));
    }
    float s0 = 0.f, s1 = 0.f;
    #pragma unroll
    for (int j = 0; j < 8; j++) {
        d[j][0] = __expf(d[j][0] - mx0); d[j][1] = __expf(d[j][1] - mx0);
        d[j][2] = __expf(d[j][2] - mx1); d[j][3] = __expf(d[j][3] - mx1);
        s0 += d[j][0] + d[j][1];
        s1 += d[j][2] + d[j][3];
    }
    #pragma unroll
    for (int o = 1; o <= 2; o <<= 1) {
        s0 += __shfl_xor_sync(0xffffffffu, s0, o);
        s1 += __shfl_xor_sync(0xffffffffu, s1, o);
    }
    float i0 = 1.f / s0, i1 = 1.f / s1;
    // store k1 split into As (warp-private rows; n-adjacent pairs)
    #pragma unroll
    for (int j = 0; j < 8; j++) {
        int np = j * 4 + tg;
        h2split(d[j][0] * i0, d[j][1] * i0, AsH[r0 * HSTR + np], AsL[r0 * HSTR + np]);
        h2split(d[j][2] * i1, d[j][3] * i1, AsH[(r0 + 8) * HSTR + np], AsL[(r0 + 8) * HSTR + np]);
    }
    // reuse d as the GEMM-2 accumulator
    #pragma unroll
    for (int j = 0; j < 8; j++)
        #pragma unroll
        for (int q = 0; q < 4; q++) d[j][q] = 0.f;
    __syncthreads();                 // all warps done with Bs(nc); k1 stores visible
    const float* Wg = g_w + (size_t)p * Mm * Dd;
    for (int e = t; e < 2048; e += 256) {
        int k = e >> 5, dp = e & 31;
        float2 v = *(const float2*)&Wg[k * 64 + 2 * dp];
        h2split(v.x, v.y, BsH[k * HSTR + dp], BsL[k * HSTR + dp]);
    }
    __syncthreads();
    uint32_t wbH = (uint32_t)__cvta_generic_to_shared(BsH);
    uint32_t wbL = (uint32_t)__cvta_generic_to_shared(BsL);
    // GEMM 2: X = k1 @ W
    #pragma unroll
    for (int ks = 0; ks < 4; ks++) {
        int kp0 = 8 * ks + tg;
        uint32_t ah[4], al[4];
        afrag(AsH, AsL, r0, kp0, ah, al);
        int krow = 16 * ks + lrow;
        #pragma unroll
        for (int j = 0; j < 8; j++) {
            uint32_t off = (uint32_t)((krow * HSTR + j * 4) * 4);
            uint32_t bh0, bh1, bl0, bl1;
            ldsm2t(bh0, bh1, wbH + off);
            ldsm2t(bl0, bl1, wbL + off);
            mma3(d[j], ah, al, bh0, bh1, bl0, bl1);
        }
    }
    size_t row0 = (size_t)p * Nn + n0 + r0;
    #pragma unroll
    for (int j = 0; j < 8; j++) {
        int c0 = j * 8 + 2 * tg;
        *(float2*)&out[row0 * Dd + c0]       = make_float2(d[j][0], d[j][1]);
        *(float2*)&out[(row0 + 8) * Dd + c0] = make_float2(d[j][2], d[j][3]);
    }
}
#define XF_SMEM_BYTES (13824 * 4)

// ---------------- launch ----------------
extern "C" void kernel_launch(void* const* d_in, const int* in_sizes, int n_in,
                              void* d_out, int out_size) {
    const float* Q = (const float*)d_in[0];
    const float* K = (const float*)d_in[1];
    const float* V = (const float*)d_in[2];
    float* out = (float*)d_out;

    cudaFuncSetAttribute(gather_u_k, cudaFuncAttributeMaxDynamicSharedMemorySize, GU_SMEM_BYTES);
    cudaFuncSetAttribute(flash_rv_k, cudaFuncAttributeMaxDynamicSharedMemorySize, FLASH_SMEM_BYTES);
    cudaFuncSetAttribute(newton_k,   cudaFuncAttributeMaxDynamicSharedMemorySize, NEWTON_SMEM_BYTES);
    cudaFuncSetAttribute(x_fused_k,  cudaFuncAttributeMaxDynamicSharedMemorySize, XF_SMEM_BYTES);

    scores_k  <<<Pp * Nn / 8, dim3(32, 8)>>>(Q, K);
    topk_k    <<<2 * Pp, 256>>>();
    gather_u_k<<<Pp, 256, GU_SMEM_BYTES>>>(Q, K);
    flash_rv_k<<<Pp * KSPLIT, 256, FLASH_SMEM_BYTES>>>(K, V);
    newton_k  <<<Pp, 256, NEWTON_SMEM_BYTES>>>();
    x_fused_k <<<Pp * 32, 256, XF_SMEM_BYTES>>>(Q, out);
}

// round 16
// speedup vs baseline: 1.2771x; 1.0937x over previous
#include <cuda_runtime.h>
#include <cuda_fp16.h>
#include <cfloat>
#include <cstdint>

// Problem constants
#define Bb 8
#define Hh 8
#define Nn 4096
#define Dd 64
#define Mm 64
#define Pp (Bb*Hh)        // 64 (b,h) pairs
#define KSPLIT 8

#define HSTR 36           // half2-word stride: frag reads land on banks 4g+tg (conflict-free)

// ---------------- scratch (device globals) ----------------
__device__ float g_sK [Pp*Nn];
__device__ float g_sQ [Pp*Nn];
__device__ int   g_idxK[Pp*Mm];
__device__ int   g_idxQ[Pp*Mm];
__device__ float g_nc [Pp*Mm*Dd];         // column landmarks (rows of K)
__device__ float g_nr [Pp*Mm*Dd];         // row landmarks (rows of Qs, pre-scaled 1/8)
__device__ float g_u  [Pp*Mm*Mm];
__device__ float g_rvp[(size_t)Pp*KSPLIT*Mm*Dd]; // unnormalized RV partials
__device__ float g_rss[Pp*KSPLIT*Mm];            // rowsum-of-exp partials
__device__ float g_w  [Pp*Mm*Dd];
__device__ unsigned int g_smax;

// ---------------- fp16 split helpers ----------------
__device__ __forceinline__ void h2split(float x, float y, uint32_t& h, uint32_t& l) {
    __half hx = __float2half_rn(x), hy = __float2half_rn(y);
    float rx = x - __half2float(hx), ry = y - __half2float(hy);
    __half lx = __float2half_rn(rx), ly = __float2half_rn(ry);
    h = (uint32_t)__half_as_ushort(hx) | ((uint32_t)__half_as_ushort(hy) << 16);
    l = (uint32_t)__half_as_ushort(lx) | ((uint32_t)__half_as_ushort(ly) << 16);
}

__device__ __forceinline__ void mma_f16(float* d, uint32_t a0, uint32_t a1, uint32_t a2, uint32_t a3,
                                        uint32_t b0, uint32_t b1) {
    asm volatile(
        "mma.sync.aligned.m16n8k16.row.col.f32.f16.f16.f32 "
        "{%0,%1,%2,%3},{%4,%5,%6,%7},{%8,%9},{%0,%1,%2,%3};"
        : "+f"(d[0]), "+f"(d[1]), "+f"(d[2]), "+f"(d[3])
        : "r"(a0), "r"(a1), "r"(a2), "r"(a3), "r"(b0), "r"(b1));
}
// fp16x3: D += Ah*Bh + Ah*Bl + Al*Bh
__device__ __forceinline__ void mma3(float* d, const uint32_t* ah, const uint32_t* al,
                                     uint32_t bh0, uint32_t bh1, uint32_t bl0, uint32_t bl1) {
    mma_f16(d, ah[0], ah[1], ah[2], ah[3], bh0, bh1);
    mma_f16(d, ah[0], ah[1], ah[2], ah[3], bl0, bl1);
    mma_f16(d, al[0], al[1], al[2], al[3], bh0, bh1);
}
__device__ __forceinline__ void ldsm2t(uint32_t& r0, uint32_t& r1, uint32_t saddr) {
    asm volatile("ldmatrix.sync.aligned.m8n8.x2.trans.shared.b16 {%0,%1}, [%2];"
                 : "=r"(r0), "=r"(r1) : "r"(saddr));
}
__device__ __forceinline__ void afrag(const uint32_t* H, const uint32_t* L, int r0, int kp0,
                                      uint32_t* ah, uint32_t* al) {
    ah[0] = H[r0 * HSTR + kp0];       al[0] = L[r0 * HSTR + kp0];
    ah[1] = H[(r0 + 8) * HSTR + kp0]; al[1] = L[(r0 + 8) * HSTR + kp0];
    ah[2] = H[r0 * HSTR + kp0 + 4];       al[2] = L[r0 * HSTR + kp0 + 4];
    ah[3] = H[(r0 + 8) * HSTR + kp0 + 4]; al[3] = L[(r0 + 8) * HSTR + kp0 + 4];
}

// one 64x64x64 fp16x3 MMA GEMM: C = Aform @ Bform (fp32 C, stride 68).
// A-form[r][kp] packs (M[r][2kp], M[r][2kp+1]); B-form[n][kp] packs (B[n][2kp], B[n][2kp+1])
// i.e. the MMA computes C[r][c] = sum_k A[r][k] * B[c][k].
__device__ __forceinline__ void mmaC64(float* C,
                                       const uint32_t* AH, const uint32_t* AL,
                                       const uint32_t* BH, const uint32_t* BL,
                                       int r0, int nh, int g, int tg) {
    float dC[4][4] = {};
    #pragma unroll
    for (int ks = 0; ks < 4; ks++) {
        int kp0 = 8 * ks + tg;
        uint32_t ah[4], al[4];
        afrag(AH, AL, r0, kp0, ah, al);
        #pragma unroll
        for (int j = 0; j < 4; j++) {
            int c = nh * 32 + j * 8 + g;
            mma3(dC[j], ah, al,
                 BH[c * HSTR + kp0], BH[c * HSTR + kp0 + 4],
                 BL[c * HSTR + kp0], BL[c * HSTR + kp0 + 4]);
        }
    }
    #pragma unroll
    for (int j = 0; j < 4; j++) {
        int cb = nh * 32 + j * 8 + 2 * tg;
        *(float2*)&C[r0 * 68 + cb]       = make_float2(dC[j][0], dC[j][1]);
        *(float2*)&C[(r0 + 8) * 68 + cb] = make_float2(dC[j][2], dC[j][3]);
    }
}
// A-form split of scale*C
__device__ __forceinline__ void splitA(uint32_t* AH, uint32_t* AL, const float* C,
                                       float scale, int t) {
    for (int e = t; e < 2048; e += 256) {
        int m = e >> 5, kp = e & 31;
        float2 v = *(const float2*)&C[m * 68 + 2 * kp];
        h2split(v.x * scale, v.y * scale, AH[m * HSTR + kp], AL[m * HSTR + kp]);
    }
}
// B-form split of (coef*I + scale*C)
__device__ __forceinline__ void splitB(uint32_t* BH, uint32_t* BL, const float* C,
                                       float coef, float scale, int t) {
    for (int e = t; e < 2048; e += 256) {
        int n = e & 63, kpr = e >> 6;
        int ra = 2 * kpr, rb = ra + 1;
        float v0 = (ra == n ? coef : 0.f) + scale * C[ra * 68 + n];
        float v1 = (rb == n ? coef : 0.f) + scale * C[rb * 68 + n];
        h2split(v0, v1, BH[n * HSTR + kpr], BL[n * HSTR + kpr]);
    }
}

// ---------------- 1) scores ----------------
__global__ void scores_k(const float* __restrict__ Q, const float* __restrict__ K) {
    if (blockIdx.x == 0 && threadIdx.x == 0 && threadIdx.y == 0) g_smax = 0u;
    int row = blockIdx.x * 8 + threadIdx.y;
    if (row >= Pp * Nn) return;
    int lane = threadIdx.x;
    const float* q = Q + (size_t)row * Dd;
    const float* k = K + (size_t)row * Dd;
    float sq = q[lane] + q[lane + 32];
    float sk = k[lane] + k[lane + 32];
    #pragma unroll
    for (int o = 16; o; o >>= 1) {
        sq += __shfl_xor_sync(0xffffffffu, sq, o);
        sk += __shfl_xor_sync(0xffffffffu, sk, o);
    }
    if (lane == 0) { g_sQ[row] = sq; g_sK[row] = sk; }
}

// ---------------- 2) top-64 via 4-pass radix select ----------------
__global__ void __launch_bounds__(256) topk_k() {
    __shared__ unsigned key[Nn];
    __shared__ unsigned hist[256];
    __shared__ unsigned sh_pref;
    __shared__ int      sh_krem;
    __shared__ unsigned sh_cnt, sh_tie;
    __shared__ int      tiebuf[64];
    int p   = blockIdx.x & (Pp - 1);
    bool isK = blockIdx.x < Pp;
    const float* src = (isK ? g_sK : g_sQ) + (size_t)p * Nn;
    int* dst = (isK ? g_idxK : g_idxQ) + p * Mm;
    int t = threadIdx.x;
    for (int i = t; i < Nn; i += 256) {
        unsigned u = __float_as_uint(src[i]);
        key[i] = u ^ ((unsigned)((int)u >> 31) | 0x80000000u);
    }
    if (t == 0) { sh_pref = 0u; sh_krem = Mm; sh_cnt = 0u; sh_tie = 0u; }
    __syncthreads();
    #pragma unroll
    for (int b = 3; b >= 0; b--) {
        hist[t] = 0u;
        __syncthreads();
        unsigned maskHi = (b == 3) ? 0u : (0xFFFFFFFFu << ((b + 1) * 8));
        unsigned pref = sh_pref;
        for (int i = t; i < Nn; i += 256) {
            unsigned k = key[i];
            if ((k & maskHi) == pref)
                atomicAdd(&hist[(k >> (b * 8)) & 0xFFu], 1u);
        }
        __syncthreads();
        if (t == 0) {
            int krem = sh_krem, acc = 0, bsel = 0;
            for (int bin = 255; bin >= 0; bin--) {
                int c = (int)hist[bin];
                if (acc + c >= krem) { bsel = bin; break; }
                acc += c;
            }
            sh_krem = krem - acc;
            sh_pref = sh_pref | ((unsigned)bsel << (b * 8));
        }
        __syncthreads();
    }
    unsigned T = sh_pref;
    for (int i = t; i < Nn; i += 256) {
        unsigned k = key[i];
        if (k > T) {
            unsigned pos = atomicAdd(&sh_cnt, 1u);
            dst[pos] = i;
        } else if (k == T) {
            unsigned tp = atomicAdd(&sh_tie, 1u);
            if (tp < 64u) tiebuf[tp] = i;
        }
    }
    __syncthreads();
    if (t == 0) {
        int n = (int)min(sh_tie, 64u);
        for (int i = 1; i < n; i++) {
            int v = tiebuf[i], j = i - 1;
            while (j >= 0 && tiebuf[j] > v) { tiebuf[j + 1] = tiebuf[j]; j--; }
            tiebuf[j + 1] = v;
        }
        int base = (int)sh_cnt, krem = sh_krem;
        for (int j = 0; j < krem; j++) dst[base + j] = tiebuf[j];
    }
}

// ---------------- 3) gather landmarks + u = row_softmax(nr @ nc^T) + colsum/smax (fp16x3 MMA) ----------------
__global__ void __launch_bounds__(256) gather_u_k(const float* __restrict__ Q,
                                                  const float* __restrict__ K) {
    extern __shared__ uint32_t smu[];
    uint32_t* ArH = smu;              // nr A-form [64][HSTR]
    uint32_t* ArL = smu + 2304;
    uint32_t* BcH = smu + 4608;       // nc B-form (natural row-major) [64][HSTR]
    uint32_t* BcL = smu + 6912;
    float*    su  = (float*)(smu + 9216);   // [64][68] fp32
    int p = blockIdx.x, t = threadIdx.x;
    const int* idxK = g_idxK + p * Mm;
    const int* idxQ = g_idxQ + p * Mm;
    for (int e = t; e < 1024; e += 256) {
        int m = e >> 4, q4 = e & 15;
        const float* qrow = Q + ((size_t)p * Nn + idxQ[m]) * Dd;
        const float* krow = K + ((size_t)p * Nn + idxK[m]) * Dd;
        float4 qv = *(const float4*)&qrow[4 * q4];
        float4 kv = *(const float4*)&krow[4 * q4];
        qv.x *= 0.125f; qv.y *= 0.125f; qv.z *= 0.125f; qv.w *= 0.125f;
        uint32_t h0, l0, h1, l1;
        h2split(qv.x, qv.y, h0, l0); h2split(qv.z, qv.w, h1, l1);
        *(uint2*)&ArH[m * HSTR + 2 * q4] = make_uint2(h0, h1);
        *(uint2*)&ArL[m * HSTR + 2 * q4] = make_uint2(l0, l1);
        h2split(kv.x, kv.y, h0, l0); h2split(kv.z, kv.w, h1, l1);
        *(uint2*)&BcH[m * HSTR + 2 * q4] = make_uint2(h0, h1);
        *(uint2*)&BcL[m * HSTR + 2 * q4] = make_uint2(l0, l1);
        *(float4*)&g_nr[p * 4096 + m * 64 + 4 * q4] = qv;
        *(float4*)&g_nc[p * 4096 + m * 64 + 4 * q4] = kv;
    }
    __syncthreads();
    int w = t >> 5, lane = t & 31, g = lane >> 2, tg = lane & 3;
    int mt = w & 3, nh = w >> 2;
    int r0 = mt * 16 + g;
    mmaC64(su, ArH, ArL, BcH, BcL, r0, nh, g, tg);   // su = nr @ nc^T
    __syncthreads();
    if (t < 64) {
        float mx = -FLT_MAX;
        for (int c = 0; c < 64; c++) mx = fmaxf(mx, su[t * 68 + c]);
        float s = 0.f;
        for (int c = 0; c < 64; c++) s += __expf(su[t * 68 + c] - mx);
        float inv = 1.f / s;
        for (int c = 0; c < 64; c++) {
            float v = __expf(su[t * 68 + c] - mx) * inv;
            su[t * 68 + c] = v;
            g_u[p * 4096 + t * 64 + c] = v;
        }
    }
    __syncthreads();
    if (t < 64) {
        float cs = 0.f;
        for (int i = 0; i < 64; i++) cs += su[i * 68 + t];
        atomicMax((int*)&g_smax, __float_as_int(cs));
    }
}
#define GU_SMEM_BYTES ((9216 + 4352) * 4)

// ---------------- 4) flash RV (fp16x3, R9 structure, float4 fills) ----------------
__global__ void __launch_bounds__(256) flash_rv_k(const float* __restrict__ K,
                                                  const float* __restrict__ V) {
    extern __shared__ uint32_t smu[];
    uint32_t* AsH = smu;            // nr split [64 m][HSTR]
    uint32_t* AsL = smu + 2304;
    uint32_t* PsH = smu + 4608;     // P split  [64 m][HSTR]
    uint32_t* PsL = smu + 6912;
    uint32_t* BsH = smu + 9216;     // K then V [64 rows][HSTR]
    uint32_t* BsL = smu + 11520;
    float*    red = (float*)(smu + 13824);
    int p  = blockIdx.x >> 3;
    int ch = blockIdx.x & 7;
    int t = threadIdx.x;
    for (int e = t; e < 1024; e += 256) {
        int m = e >> 4, q4 = e & 15;
        float4 v = *(const float4*)&g_nr[p * 4096 + m * 64 + 4 * q4];
        uint32_t h0, l0, h1, l1;
        h2split(v.x, v.y, h0, l0); h2split(v.z, v.w, h1, l1);
        *(uint2*)&AsH[m * HSTR + 2 * q4] = make_uint2(h0, h1);
        *(uint2*)&AsL[m * HSTR + 2 * q4] = make_uint2(l0, l1);
    }
    const float* Kp = K + (size_t)p * Nn * Dd;
    const float* Vp = V + (size_t)p * Nn * Dd;
    int w = t >> 5, lane = t & 31, g = lane >> 2, tg = lane & 3;
    int mt = w & 3, nh = w >> 2;
    int r0 = mt * 16 + g;
    int lrow = lane & 15;
    uint32_t vbH = (uint32_t)__cvta_generic_to_shared(BsH);
    uint32_t vbL = (uint32_t)__cvta_generic_to_shared(BsL);
    float dRV[4][4] = {};
    float rs0 = 0.f, rs1 = 0.f;
    for (int nt = 0; nt < 8; nt++) {
        int nb = ch * 512 + nt * 64;
        __syncthreads();                        // prior RV-MMA done before Bs overwrite
        for (int e = t; e < 1024; e += 256) {   // Bs = K rows (float4)
            int n = e >> 4, q4 = e & 15;
            float4 v = *(const float4*)&Kp[(size_t)(nb + n) * Dd + 4 * q4];
            uint32_t h0, l0, h1, l1;
            h2split(v.x, v.y, h0, l0); h2split(v.z, v.w, h1, l1);
            *(uint2*)&BsH[n * HSTR + 2 * q4] = make_uint2(h0, h1);
            *(uint2*)&BsL[n * HSTR + 2 * q4] = make_uint2(l0, l1);
        }
        __syncthreads();
        float dS[4][4] = {};
        #pragma unroll
        for (int ks = 0; ks < 4; ks++) {
            int kp0 = 8 * ks + tg;
            uint32_t ah[4], al[4];
            afrag(AsH, AsL, r0, kp0, ah, al);
            #pragma unroll
            for (int j = 0; j < 4; j++) {
                int c = nh * 32 + j * 8 + g;
                mma3(dS[j], ah, al,
                     BsH[c * HSTR + kp0], BsH[c * HSTR + kp0 + 4],
                     BsL[c * HSTR + kp0], BsL[c * HSTR + kp0 + 4]);
            }
        }
        #pragma unroll
        for (int j = 0; j < 4; j++) {
            int np = nh * 16 + j * 4 + tg;
            float e00 = __expf(dS[j][0]), e01 = __expf(dS[j][1]);
            float e10 = __expf(dS[j][2]), e11 = __expf(dS[j][3]);
            rs0 += e00 + e01; rs1 += e10 + e11;
            h2split(e00, e01, PsH[r0 * HSTR + np], PsL[r0 * HSTR + np]);
            h2split(e10, e11, PsH[(r0 + 8) * HSTR + np], PsL[(r0 + 8) * HSTR + np]);
        }
        __syncthreads();                        // P complete; Bs free
        for (int e = t; e < 1024; e += 256) {   // Bs = V rows (float4)
            int n = e >> 4, q4 = e & 15;
            float4 v = *(const float4*)&Vp[(size_t)(nb + n) * Dd + 4 * q4];
            uint32_t h0, l0, h1, l1;
            h2split(v.x, v.y, h0, l0); h2split(v.z, v.w, h1, l1);
            *(uint2*)&BsH[n * HSTR + 2 * q4] = make_uint2(h0, h1);
            *(uint2*)&BsL[n * HSTR + 2 * q4] = make_uint2(l0, l1);
        }
        __syncthreads();
        #pragma unroll
        for (int ks = 0; ks < 4; ks++) {
            int kp0 = 8 * ks + tg;
            uint32_t ah[4], al[4];
            afrag(PsH, PsL, r0, kp0, ah, al);
            int krow = 16 * ks + lrow;
            #pragma unroll
            for (int j = 0; j < 4; j++) {
                uint32_t off = (uint32_t)((krow * HSTR + nh * 16 + j * 4) * 4);
                uint32_t bh0, bh1, bl0, bl1;
                ldsm2t(bh0, bh1, vbH + off);
                ldsm2t(bl0, bl1, vbL + off);
                mma3(dRV[j], ah, al, bh0, bh1, bl0, bl1);
            }
        }
    }
    #pragma unroll
    for (int o = 1; o <= 2; o <<= 1) {
        rs0 += __shfl_xor_sync(0xffffffffu, rs0, o);
        rs1 += __shfl_xor_sync(0xffffffffu, rs1, o);
    }
    __syncthreads();
    if (tg == 0) { red[nh * 64 + r0] = rs0; red[nh * 64 + r0 + 8] = rs1; }
    __syncthreads();
    if (t < 64) g_rss[(p * KSPLIT + ch) * 64 + t] = red[t] + red[64 + t];
    float* out = g_rvp + ((size_t)blockIdx.x << 12);
    #pragma unroll
    for (int j = 0; j < 4; j++) {
        int cb = nh * 32 + j * 8 + 2 * tg;
        *(float2*)&out[r0 * 64 + cb]       = make_float2(dRV[j][0], dRV[j][1]);
        *(float2*)&out[(r0 + 8) * 64 + cb] = make_float2(dRV[j][2], dRV[j][3]);
    }
}
#define FLASH_SMEM_BYTES ((13824 + 128) * 4)

// ---------------- 5) Newton-Schulz on tensor cores (fp16x3) + fused RV merge + W = Vinv @ RV ----------------
__global__ void __launch_bounds__(256) newton_k() {
    extern __shared__ uint32_t smu[];
    uint32_t* KmH = smu;              // A-form Km (const)
    uint32_t* KmL = smu + 2304;
    uint32_t* VAH = smu + 4608;       // A-form V
    uint32_t* VAL = smu + 6912;
    uint32_t* VBH = smu + 9216;       // B-form V
    uint32_t* VBL = smu + 11520;
    uint32_t* TBH = smu + 13824;      // B-form T (polynomial operand; reused for RV at end)
    uint32_t* TBL = smu + 16128;
    uint32_t* XAH = smu + 18432;      // A-form KV
    uint32_t* XAL = smu + 20736;
    float*    C   = (float*)(smu + 23040);        // [64][68] fp32
    float*    sden= (float*)(smu + 23040 + 4352); // [64]
    int p = blockIdx.x, t = threadIdx.x;
    if (t < 64) {
        float den = 0.f;
        #pragma unroll
        for (int ch = 0; ch < KSPLIT; ch++) den += g_rss[(p * KSPLIT + ch) * 64 + t];
        sden[t] = 1.f / den;
    }
    float invs = 1.f / __int_as_float((int)g_smax);
    const float* up = g_u + p * 4096;
    for (int e = t; e < 2048; e += 256) {
        int m = e >> 5, kp = e & 31;
        float2 v = *(const float2*)&up[m * 64 + 2 * kp];
        h2split(v.x, v.y, KmH[m * HSTR + kp], KmL[m * HSTR + kp]);
        h2split(v.x * invs, v.y * invs, VBH[m * HSTR + kp], VBL[m * HSTR + kp]);
    }
    for (int e = t; e < 2048; e += 256) {
        int r = e & 63, kp = e >> 6;
        float a = up[(2 * kp) * 64 + r] * invs;
        float b = up[(2 * kp + 1) * 64 + r] * invs;
        h2split(a, b, VAH[r * HSTR + kp], VAL[r * HSTR + kp]);
    }
    __syncthreads();
    int w = t >> 5, lane = t & 31, g = lane >> 2, tg = lane & 3;
    int mt = w & 3, nh = w >> 2;
    int r0 = mt * 16 + g;
    for (int it = 0; it < 6; it++) {
        mmaC64(C, KmH, KmL, VBH, VBL, r0, nh, g, tg);   // C = KV = Km @ V
        __syncthreads();
        splitA(XAH, XAL, C, 1.0f, t);                   // XA = KV
        splitB(TBH, TBL, C, 7.f, -1.f, t);              // TB = 7I - KV
        __syncthreads();
        mmaC64(C, XAH, XAL, TBH, TBL, r0, nh, g, tg);   // C = KV @ (7I - KV)
        __syncthreads();
        splitB(TBH, TBL, C, 15.f, -1.f, t);             // TB = 15I - C
        __syncthreads();
        mmaC64(C, XAH, XAL, TBH, TBL, r0, nh, g, tg);   // C = KV @ (15I - ...)
        __syncthreads();
        splitB(TBH, TBL, C, 13.f, -1.f, t);             // TB = 13I - C
        __syncthreads();
        mmaC64(C, VAH, VAL, TBH, TBL, r0, nh, g, tg);   // C = V @ (13I - ...) = 4*Vnew
        __syncthreads();
        splitA(VAH, VAL, C, 0.25f, t);                  // V A-form
        splitB(VBH, VBL, C, 0.f, 0.25f, t);             // V B-form
        __syncthreads();
    }
    for (int e = t; e < 2048; e += 256) {
        int n = e & 63, kpr = e >> 6;
        int ra = 2 * kpr, rb = ra + 1;
        float s0 = 0.f, s1 = 0.f;
        #pragma unroll
        for (int ch = 0; ch < KSPLIT; ch++) {
            const float* part = g_rvp + (((size_t)(p * KSPLIT + ch)) << 12);
            s0 += part[ra * 64 + n];
            s1 += part[rb * 64 + n];
        }
        h2split(s0 * sden[ra], s1 * sden[rb], TBH[n * HSTR + kpr], TBL[n * HSTR + kpr]);
    }
    __syncthreads();
    {
        float dC[4][4] = {};
        #pragma unroll
        for (int ks = 0; ks < 4; ks++) {
            int kp0 = 8 * ks + tg;
            uint32_t ah[4], al[4];
            afrag(VAH, VAL, r0, kp0, ah, al);
            #pragma unroll
            for (int j = 0; j < 4; j++) {
                int c = nh * 32 + j * 8 + g;
                mma3(dC[j], ah, al,
                     TBH[c * HSTR + kp0], TBH[c * HSTR + kp0 + 4],
                     TBL[c * HSTR + kp0], TBL[c * HSTR + kp0 + 4]);
            }
        }
        float* Wp = g_w + p * 4096;
        #pragma unroll
        for (int j = 0; j < 4; j++) {
            int cb = nh * 32 + j * 8 + 2 * tg;
            *(float2*)&Wp[r0 * 64 + cb]       = make_float2(dC[j][0], dC[j][1]);
            *(float2*)&Wp[(r0 + 8) * 64 + cb] = make_float2(dC[j][2], dC[j][3]);
        }
    }
}
#define NEWTON_SMEM_BYTES ((23040 + 4352 + 64) * 4)

// ---------------- 6) fused X (fp16x3, float4 fills): c -> softmax -> @W -> out ----------------
__global__ void __launch_bounds__(256) x_fused_k(const float* __restrict__ Q,
                                                 float* __restrict__ out) {
    extern __shared__ uint32_t smu[];
    uint32_t* AsH = smu;            // Q tile, then k1 tile [128][HSTR]
    uint32_t* AsL = smu + 4608;
    uint32_t* BsH = smu + 9216;     // nc, then W [64][HSTR]
    uint32_t* BsL = smu + 11520;
    int p  = blockIdx.x >> 5;
    int n0 = (blockIdx.x & 31) * 128;
    int t = threadIdx.x;
    const float* Ag = Q + ((size_t)p * Nn + n0) * Dd;
    for (int e = t; e < 2048; e += 256) {
        int m = e >> 4, q4 = e & 15;
        float4 v = *(const float4*)&Ag[m * 64 + 4 * q4];
        uint32_t h0, l0, h1, l1;
        h2split(v.x * 0.125f, v.y * 0.125f, h0, l0);
        h2split(v.z * 0.125f, v.w * 0.125f, h1, l1);
        *(uint2*)&AsH[m * HSTR + 2 * q4] = make_uint2(h0, h1);
        *(uint2*)&AsL[m * HSTR + 2 * q4] = make_uint2(l0, l1);
    }
    const float* Bg = g_nc + (size_t)p * Mm * Dd;
    for (int e = t; e < 1024; e += 256) {
        int c = e >> 4, q4 = e & 15;
        float4 v = *(const float4*)&Bg[c * 64 + 4 * q4];
        uint32_t h0, l0, h1, l1;
        h2split(v.x, v.y, h0, l0); h2split(v.z, v.w, h1, l1);
        *(uint2*)&BsH[c * HSTR + 2 * q4] = make_uint2(h0, h1);
        *(uint2*)&BsL[c * HSTR + 2 * q4] = make_uint2(l0, l1);
    }
    __syncthreads();
    int w = t >> 5, lane = t & 31, g = lane >> 2, tg = lane & 3;
    int r0 = w * 16 + g;
    int lrow = lane & 15;
    // GEMM 1: c = Qs @ nc^T
    float d[8][4] = {};
    #pragma unroll
    for (int ks = 0; ks < 4; ks++) {
        int kp0 = 8 * ks + tg;
        uint32_t ah[4], al[4];
        afrag(AsH, AsL, r0, kp0, ah, al);
        #pragma unroll
        for (int j = 0; j < 8; j++) {
            int c = j * 8 + g;
            mma3(d[j], ah, al,
                 BsH[c * HSTR + kp0], BsH[c * HSTR + kp0 + 4],
                 BsL[c * HSTR + kp0], BsL[c * HSTR + kp0 + 4]);
        }
    }
    // exact row softmax over the 4-lane group
    float mx0 = -FLT_MAX, mx1 = -FLT_MAX;
    #pragma unroll
    for (int j = 0; j < 8; j++) {
        mx0 = fmaxf(mx0, fmaxf(d[j][0], d[j][1]));
        mx1 = fmaxf(mx1, fmaxf(d[j][2], d[j][3]));
    }
    #pragma unroll
    for (int o = 1; o <= 2; o <<= 1) {
        mx0 = fmaxf(mx0, __shfl_xor_sync(0xffffffffu, mx0, o));
        mx1 = fmaxf(mx1, __shfl_xor_sync(0xffffffffu, mx1, o));
    }
    float s0 = 0.f, s1 = 0.f;
    #pragma unroll
    for (int j = 0; j < 8; j++) {
        d[j][0] = __expf(d[j][0] - mx0); d[j][1] = __expf(d[j][1] - mx0);
        d[j][2] = __expf(d[j][2] - mx1); d[j][3] = __expf(d[j][3] - mx1);
        s0 += d[j][0] + d[j][1];
        s1 += d[j][2] + d[j][3];
    }
    #pragma unroll
    for (int o = 1; o <= 2; o <<= 1) {
        s0 += __shfl_xor_sync(0xffffffffu, s0, o);
        s1 += __shfl_xor_sync(0xffffffffu, s1, o);
    }
    float i0 = 1.f / s0, i1 = 1.f / s1;
    // store k1 split into As (warp-private rows; n-adjacent pairs)
    #pragma unroll
    for (int j = 0; j < 8; j++) {
        int np = j * 4 + tg;
        h2split(d[j][0] * i0, d[j][1] * i0, AsH[r0 * HSTR + np], AsL[r0 * HSTR + np]);
        h2split(d[j][2] * i1, d[j][3] * i1, AsH[(r0 + 8) * HSTR + np], AsL[(r0 + 8) * HSTR + np]);
    }
    // reuse d as the GEMM-2 accumulator
    #pragma unroll
    for (int j = 0; j < 8; j++)
        #pragma unroll
        for (int q = 0; q < 4; q++) d[j][q] = 0.f;
    __syncthreads();                 // all warps done with Bs(nc); k1 stores visible
    const float* Wg = g_w + (size_t)p * Mm * Dd;
    for (int e = t; e < 1024; e += 256) {
        int k = e >> 4, q4 = e & 15;
        float4 v = *(const float4*)&Wg[k * 64 + 4 * q4];
        uint32_t h0, l0, h1, l1;
        h2split(v.x, v.y, h0, l0); h2split(v.z, v.w, h1, l1);
        *(uint2*)&BsH[k * HSTR + 2 * q4] = make_uint2(h0, h1);
        *(uint2*)&BsL[k * HSTR + 2 * q4] = make_uint2(l0, l1);
    }
    __syncthreads();
    uint32_t wbH = (uint32_t)__cvta_generic_to_shared(BsH);
    uint32_t wbL = (uint32_t)__cvta_generic_to_shared(BsL);
    // GEMM 2: X = k1 @ W
    #pragma unroll
    for (int ks = 0; ks < 4; ks++) {
        int kp0 = 8 * ks + tg;
        uint32_t ah[4], al[4];
        afrag(AsH, AsL, r0, kp0, ah, al);
        int krow = 16 * ks + lrow;
        #pragma unroll
        for (int j = 0; j < 8; j++) {
            uint32_t off = (uint32_t)((krow * HSTR + j * 4) * 4);
            uint32_t bh0, bh1, bl0, bl1;
            ldsm2t(bh0, bh1, wbH + off);
            ldsm2t(bl0, bl1, wbL + off);
            mma3(d[j], ah, al, bh0, bh1, bl0, bl1);
        }
    }
    size_t row0 = (size_t)p * Nn + n0 + r0;
    #pragma unroll
    for (int j = 0; j < 8; j++) {
        int c0 = j * 8 + 2 * tg;
        *(float2*)&out[row0 * Dd + c0]       = make_float2(d[j][0], d[j][1]);
        *(float2*)&out[(row0 + 8) * Dd + c0] = make_float2(d[j][2], d[j][3]);
    }
}
#define XF_SMEM_BYTES (13824 * 4)

// ---------------- launch ----------------
extern "C" void kernel_launch(void* const* d_in, const int* in_sizes, int n_in,
                              void* d_out, int out_size) {
    const float* Q = (const float*)d_in[0];
    const float* K = (const float*)d_in[1];
    const float* V = (const float*)d_in[2];
    float* out = (float*)d_out;

    cudaFuncSetAttribute(gather_u_k, cudaFuncAttributeMaxDynamicSharedMemorySize, GU_SMEM_BYTES);
    cudaFuncSetAttribute(flash_rv_k, cudaFuncAttributeMaxDynamicSharedMemorySize, FLASH_SMEM_BYTES);
    cudaFuncSetAttribute(newton_k,   cudaFuncAttributeMaxDynamicSharedMemorySize, NEWTON_SMEM_BYTES);
    cudaFuncSetAttribute(x_fused_k,  cudaFuncAttributeMaxDynamicSharedMemorySize, XF_SMEM_BYTES);

    scores_k  <<<Pp * Nn / 8, dim3(32, 8)>>>(Q, K);
    topk_k    <<<2 * Pp, 256>>>();
    gather_u_k<<<Pp, 256, GU_SMEM_BYTES>>>(Q, K);
    flash_rv_k<<<Pp * KSPLIT, 256, FLASH_SMEM_BYTES>>>(K, V);
    newton_k  <<<Pp, 256, NEWTON_SMEM_BYTES>>>();
    x_fused_k <<<Pp * 32, 256, XF_SMEM_BYTES>>>(Q, out);
}